// round 8
// baseline (speedup 1.0000x reference)
#include <cuda_runtime.h>
#include <cuda_bf16.h>
#include <math.h>

typedef unsigned int u32;

#define BB   256
#define TT   512
#define HH   256
#define LL   4
#define NBLK 128
#define NTHR 256
#define GRP  16          // blocks per barrier group (same bt)

#define AS   132         // A row stride (words)
#define BSB  132         // B row stride (words)
#define GS   33          // gate smem row stride

#define SZ_A (64 * AS)   // 8448 words
#define SZ_B (32 * BSB)  // 4224 words
#define SZ_G (64 * GS)   // 2112 words

#define OFF_AHH_HI 0
#define OFF_AHH_LO (SZ_A)
#define OFF_AIH_HI (2 * SZ_A)
#define OFF_AIH_LO (3 * SZ_A)
#define OFF_B      (4 * SZ_A)                 // [B0hi][B0lo][B1hi][B1lo], SZ_B each
#define OFF_G      (4 * SZ_A + 4 * SZ_B)
#define OFF_BSN    (OFF_G + SZ_G)
#define OFF_BS0    (OFF_BSN + 64)
#define OFF_WXS    (OFF_BS0 + 64)
#define OFF_XS     (OFF_WXS + 64)
#define SMEM_WORDS (OFF_XS + 32)
#define SMEM_BYTES (SMEM_WORDS * 4)           // ~207 KB

// ---------------- device scratch ----------------
__device__ __align__(128) u32 g_hAhi[(size_t)TT * BB * 128];
__device__ __align__(128) u32 g_hAlo[(size_t)TT * BB * 128];
__device__ __align__(128) u32 g_hBhi[(size_t)TT * BB * 128];
__device__ __align__(128) u32 g_hBlo[(size_t)TT * BB * 128];
__device__ __align__(128) float g_gih[(size_t)NBLK * TT * 2048];
__device__ unsigned g_bar[8 * LL * TT];
__device__ unsigned g_fin;

struct Params {
    const float* x;
    const float* Wih[LL];
    const float* Whh[LL];
    const float* bih[LL];
    const float* bhh[LL];
    const float* fcW;
    const float* fcb;
    float* out;
};

// ---------------- helpers ----------------
__device__ __forceinline__ float sigf(float v) {
    return __fdividef(1.0f, 1.0f + __expf(-v));
}
__device__ __forceinline__ float tanhfast(float v) {
    return 1.0f - __fdividef(2.0f, __expf(2.0f * v) + 1.0f);
}

__device__ __forceinline__ void split_pack(float x, float y, u32& hi, u32& lo) {
    __nv_bfloat162 h2, l2;
    h2.x = __float2bfloat16_rn(x);
    h2.y = __float2bfloat16_rn(y);
    l2.x = __float2bfloat16_rn(x - __bfloat162float(h2.x));
    l2.y = __float2bfloat16_rn(y - __bfloat162float(h2.y));
    hi = *reinterpret_cast<u32*>(&h2);
    lo = *reinterpret_cast<u32*>(&l2);
}

__device__ __forceinline__ void mma16816(float c[4], u32 a0, u32 a1, u32 a2, u32 a3,
                                         u32 b0, u32 b1) {
    asm("mma.sync.aligned.m16n8k16.row.col.f32.bf16.bf16.f32 "
        "{%0,%1,%2,%3}, {%4,%5,%6,%7}, {%8,%9}, {%0,%1,%2,%3};"
        : "+f"(c[0]), "+f"(c[1]), "+f"(c[2]), "+f"(c[3])
        : "r"(a0), "r"(a1), "r"(a2), "r"(a3), "r"(b0), "r"(b1));
}
__device__ __forceinline__ void mma4(float c[4], const u32 a[4], u32 b0, u32 b1) {
    mma16816(c, a[0], a[1], a[2], a[3], b0, b1);
}

__device__ __forceinline__ void ldsm4(u32& r0, u32& r1, u32& r2, u32& r3, u32 addr) {
    asm volatile("ldmatrix.sync.aligned.m8n8.x4.shared.b16 {%0,%1,%2,%3}, [%4];"
                 : "=r"(r0), "=r"(r1), "=r"(r2), "=r"(r3) : "r"(addr));
}

// compute-warpgroup barrier (warps 0-3, 128 threads, named barrier 1)
__device__ __forceinline__ void cbar() {
    asm volatile("bar.sync 1, 128;" ::: "memory");
}

__device__ __forceinline__ void poll_ge(unsigned* p, unsigned target) {
    unsigned v;
    asm volatile("ld.acquire.gpu.global.u32 %0, [%1];" : "=r"(v) : "l"(p) : "memory");
    while (v < target) {
        __nanosleep(32);
        asm volatile("ld.acquire.gpu.global.u32 %0, [%1];" : "=r"(v) : "l"(p) : "memory");
    }
}
__device__ __forceinline__ void arrive1(unsigned* p) {
    asm volatile("red.release.gpu.global.add.u32 [%0], %1;" :: "l"(p), "r"(1u) : "memory");
}

__device__ __forceinline__ void load_W(const float* __restrict__ W, int j0,
                                       u32* __restrict__ shi, u32* __restrict__ slo) {
    for (int i = threadIdx.x; i < 64 * 128; i += NTHR) {
        const int m = i >> 7;
        const int k2 = i & 127;
        const int row = (m >> 4) * HH + j0 + (m & 15);
        const float2 w = *(const float2*)(W + (size_t)row * HH + 2 * k2);
        split_pack(w.x, w.y, shi[m * AS + k2], slo[m * AS + k2]);
    }
}

// ---------------- kernel ----------------
__global__ void __launch_bounds__(NTHR, 1) lstm_ws(Params p) {
    extern __shared__ u32 sm[];
    u32* sAhhHi = sm + OFF_AHH_HI;
    u32* sAhhLo = sm + OFF_AHH_LO;
    u32* sAihHi = sm + OFF_AIH_HI;
    u32* sAihLo = sm + OFF_AIH_LO;
    float* gsm  = (float*)(sm + OFF_G);
    float* bsn  = (float*)(sm + OFF_BSN);
    float* bs0  = (float*)(sm + OFF_BS0);
    float* wxs  = (float*)(sm + OFF_WXS);
    float* xs   = (float*)(sm + OFF_XS);

    const int tid  = threadIdx.x;
    const int bid  = blockIdx.x;
    const int jt   = bid >> 3;
    const int bt   = bid & 7;
    const int j0   = jt * 16;
    const int b0   = bt * 32;
    const int wid  = tid >> 5;
    const int lane = tid & 31;
    const int lr   = lane >> 2;
    const int lc   = lane & 3;
    const bool comp = (wid < 4);
    const int mw   = (wid & 3) * 16;      // m-base for this warp's 16-row slice

    // fragment byte addresses
    const u32 smbase = (u32)__cvta_generic_to_shared(sm);
    const u32 arow   = (u32)(mw + ((lane >> 3) & 1) * 8 + (lane & 7));
    const u32 acol   = (u32)((lane >> 4) * 4);
    const u32 aHHhi  = smbase + (OFF_AHH_HI + arow * AS + acol) * 4;
    const u32 aHHlo  = aHHhi + SZ_A * 4;
    const u32 aIHhi  = smbase + (OFF_AIH_HI + arow * AS + acol) * 4;
    const u32 aIHlo  = aIHhi + SZ_A * 4;
    const u32 loD    = SZ_B * 4;          // hi->lo byte offset within a slot
    u32 bf[2][2];                          // [slot][n-half] hi-frag base
    #pragma unroll
    for (int s = 0; s < 2; ++s)
        #pragma unroll
        for (int nh = 0; nh < 2; ++nh) {
            const u32 brow = (u32)(nh * 16 + ((lane >> 3) & 1) * 8 + (lane & 7));
            bf[s][nh] = smbase + (OFF_B + s * 2 * SZ_B + brow * BSB + acol) * 4;
        }

    float* gG0 = g_gih + (size_t)bid * TT * 2048;
    unsigned* bars = g_bar + bt * (LL * TT);

    // cell-update ownership (compute threads, tid<128): two hidden pairs x one batch col
    const int jpA = tid >> 5;        // 0..3
    const int jpB = jpA + 4;         // 4..7
    const int bbx = lane;            // 0..31

    // persistent Whh fragments
    u32 Ah[16][4], Al[16][4];

    // initial staging
    load_W(p.Whh[0], j0, sAhhHi, sAhhLo);
    load_W(p.Wih[1], j0, sAihHi, sAihLo);
    if (tid < 64) {
        const int row = (tid >> 4) * HH + j0 + (tid & 15);
        bs0[tid] = p.bih[0][row] + p.bhh[0][row];
        wxs[tid] = p.Wih[0][row];             // W_ih0 is [4H, 1]
        bsn[tid] = p.bih[1][row] + p.bhh[1][row];
    }
    __syncthreads();
    if (comp) {
        #pragma unroll
        for (int kk = 0; kk < 16; ++kk) {
            ldsm4(Ah[kk][0], Ah[kk][1], Ah[kk][2], Ah[kk][3], aHHhi + kk * 32);
            ldsm4(Al[kk][0], Al[kk][1], Al[kk][2], Al[kk][3], aHHlo + kk * 32);
        }
    }

    for (int l = 0; l < LL; ++l) {
        u32* outhi = (l & 1) ? g_hBhi : g_hAhi;
        u32* outlo = (l & 1) ? g_hBlo : g_hAlo;
        float ccA0 = 0.f, ccA1 = 0.f, ccB0 = 0.f, ccB1 = 0.f;

        for (int t = 0; t < TT; ++t) {
            const int slot = t & 1;
            float c[4][4];

            if (comp) {
                // prefetch accumulator init before the wait
                if (l > 0) {
                    const float* gw = gG0 + (size_t)t * 2048;
                    #pragma unroll
                    for (int nb = 0; nb < 4; ++nb) {
                        const int col = nb * 8 + 2 * lc;
                        const float2 u = *(const float2*)(gw + (mw + lr) * 32 + col);
                        const float2 v = *(const float2*)(gw + (mw + 8 + lr) * 32 + col);
                        c[nb][0] = u.x; c[nb][1] = u.y; c[nb][2] = v.x; c[nb][3] = v.y;
                    }
                } else if (tid < 32) {
                    xs[tid] = p.x[(size_t)(b0 + tid) * TT + t];
                }

                if (t > 0) {
                    if (tid == 0) poll_ge(&bars[l * TT + t - 1], GRP);
                    cbar();
                    // load h(t-1) tile into slot (8 rows per compute warp)
                    u32* dhi = sm + OFF_B + slot * 2 * SZ_B;
                    u32* dlo = dhi + SZ_B;
                    #pragma unroll
                    for (int r = 0; r < 8; ++r) {
                        const int bbr = wid * 8 + r;
                        const size_t gi = ((size_t)(t - 1) * BB + b0 + bbr) * 128 + lane * 4;
                        const uint4 vh = *(const uint4*)(outhi + gi);
                        const uint4 vl = *(const uint4*)(outlo + gi);
                        *(uint4*)(dhi + bbr * BSB + lane * 4) = vh;
                        *(uint4*)(dlo + bbr * BSB + lane * 4) = vl;
                    }
                }
            }
            __syncthreads();   // B(t-1) tile (and xs) visible to all warps

            if (comp) {
                if (l == 0) {
                    const float w0 = wxs[mw + lr],     bv0 = bs0[mw + lr];
                    const float w1 = wxs[mw + 8 + lr], bv1 = bs0[mw + 8 + lr];
                    #pragma unroll
                    for (int nb = 0; nb < 4; ++nb) {
                        const float xa = xs[nb * 8 + 2 * lc];
                        const float xb = xs[nb * 8 + 2 * lc + 1];
                        c[nb][0] = fmaf(w0, xa, bv0); c[nb][1] = fmaf(w0, xb, bv0);
                        c[nb][2] = fmaf(w1, xa, bv1); c[nb][3] = fmaf(w1, xb, bv1);
                    }
                }

                if (t > 0) {
                    const u32 f0 = bf[slot][0], f1 = bf[slot][1];
                    #pragma unroll
                    for (int kk = 0; kk < 16; ++kk) {
                        u32 bh[8], bl[8];
                        ldsm4(bh[0], bh[1], bh[2], bh[3], f0 + kk * 32);
                        ldsm4(bh[4], bh[5], bh[6], bh[7], f1 + kk * 32);
                        ldsm4(bl[0], bl[1], bl[2], bl[3], f0 + loD + kk * 32);
                        ldsm4(bl[4], bl[5], bl[6], bl[7], f1 + loD + kk * 32);
                        mma4(c[0], Ah[kk], bh[0], bh[2]);
                        mma4(c[1], Ah[kk], bh[1], bh[3]);
                        mma4(c[2], Ah[kk], bh[4], bh[6]);
                        mma4(c[3], Ah[kk], bh[5], bh[7]);
                        mma4(c[0], Ah[kk], bl[0], bl[2]);
                        mma4(c[1], Ah[kk], bl[1], bl[3]);
                        mma4(c[2], Ah[kk], bl[4], bl[6]);
                        mma4(c[3], Ah[kk], bl[5], bl[7]);
                        mma4(c[0], Al[kk], bh[0], bh[2]);
                        mma4(c[1], Al[kk], bh[1], bh[3]);
                        mma4(c[2], Al[kk], bh[4], bh[6]);
                        mma4(c[3], Al[kk], bh[5], bh[7]);
                    }
                }

                // gates -> smem
                #pragma unroll
                for (int nb = 0; nb < 4; ++nb) {
                    const int col = nb * 8 + 2 * lc;
                    gsm[(mw + lr) * GS + col]         = c[nb][0];
                    gsm[(mw + lr) * GS + col + 1]     = c[nb][1];
                    gsm[(mw + 8 + lr) * GS + col]     = c[nb][2];
                    gsm[(mw + 8 + lr) * GS + col + 1] = c[nb][3];
                }
                cbar();

                // cell update: two hidden pairs per thread
                {
                    const int ja0 = 2 * jpA, ja1 = ja0 + 1;
                    const int jb0 = 2 * jpB, jb1 = jb0 + 1;
                    const float iA0 = gsm[ja0 * GS + bbx], iA1 = gsm[ja1 * GS + bbx];
                    const float fA0 = gsm[(16 + ja0) * GS + bbx], fA1 = gsm[(16 + ja1) * GS + bbx];
                    const float gA0 = gsm[(32 + ja0) * GS + bbx], gA1 = gsm[(32 + ja1) * GS + bbx];
                    const float oA0 = gsm[(48 + ja0) * GS + bbx], oA1 = gsm[(48 + ja1) * GS + bbx];
                    const float iB0 = gsm[jb0 * GS + bbx], iB1 = gsm[jb1 * GS + bbx];
                    const float fB0 = gsm[(16 + jb0) * GS + bbx], fB1 = gsm[(16 + jb1) * GS + bbx];
                    const float gB0 = gsm[(32 + jb0) * GS + bbx], gB1 = gsm[(32 + jb1) * GS + bbx];
                    const float oB0 = gsm[(48 + jb0) * GS + bbx], oB1 = gsm[(48 + jb1) * GS + bbx];

                    ccA0 = sigf(fA0) * ccA0 + sigf(iA0) * tanhfast(gA0);
                    ccA1 = sigf(fA1) * ccA1 + sigf(iA1) * tanhfast(gA1);
                    ccB0 = sigf(fB0) * ccB0 + sigf(iB0) * tanhfast(gB0);
                    ccB1 = sigf(fB1) * ccB1 + sigf(iB1) * tanhfast(gB1);
                    const float hA0 = sigf(oA0) * tanhfast(ccA0);
                    const float hA1 = sigf(oA1) * tanhfast(ccA1);
                    const float hB0 = sigf(oB0) * tanhfast(ccB0);
                    const float hB1 = sigf(oB1) * tanhfast(ccB1);

                    u32 hiA, loA, hiB, loB;
                    split_pack(hA0, hA1, hiA, loA);
                    split_pack(hB0, hB1, hiB, loB);
                    const size_t base = ((size_t)t * BB + b0 + bbx) * 128 + (j0 >> 1);
                    outhi[base + jpA] = hiA; outlo[base + jpA] = loA;
                    outhi[base + jpB] = hiB; outlo[base + jpB] = loB;
                }
                cbar();
                if (tid == 0) arrive1(&bars[l * TT + t]);
            } else if (l < 3 && t > 0) {
                // ih warps: input projection for layer l+1 on h_l(t-1)
                float c2[4][4];
                const float bn0 = bsn[mw + lr], bn1 = bsn[mw + 8 + lr];
                #pragma unroll
                for (int nb = 0; nb < 4; ++nb) {
                    c2[nb][0] = bn0; c2[nb][1] = bn0; c2[nb][2] = bn1; c2[nb][3] = bn1;
                }
                const u32 f0 = bf[slot][0], f1 = bf[slot][1];
                #pragma unroll
                for (int kk = 0; kk < 16; ++kk) {
                    u32 pa[4], qa[4], bh[8], bl[8];
                    ldsm4(pa[0], pa[1], pa[2], pa[3], aIHhi + kk * 32);
                    ldsm4(qa[0], qa[1], qa[2], qa[3], aIHlo + kk * 32);
                    ldsm4(bh[0], bh[1], bh[2], bh[3], f0 + kk * 32);
                    ldsm4(bh[4], bh[5], bh[6], bh[7], f1 + kk * 32);
                    ldsm4(bl[0], bl[1], bl[2], bl[3], f0 + loD + kk * 32);
                    ldsm4(bl[4], bl[5], bl[6], bl[7], f1 + loD + kk * 32);
                    mma4(c2[0], pa, bh[0], bh[2]);
                    mma4(c2[1], pa, bh[1], bh[3]);
                    mma4(c2[2], pa, bh[4], bh[6]);
                    mma4(c2[3], pa, bh[5], bh[7]);
                    mma4(c2[0], pa, bl[0], bl[2]);
                    mma4(c2[1], pa, bl[1], bl[3]);
                    mma4(c2[2], pa, bl[4], bl[6]);
                    mma4(c2[3], pa, bl[5], bl[7]);
                    mma4(c2[0], qa, bh[0], bh[2]);
                    mma4(c2[1], qa, bh[1], bh[3]);
                    mma4(c2[2], qa, bh[4], bh[6]);
                    mma4(c2[3], qa, bh[5], bh[7]);
                }
                float* gw = gG0 + (size_t)(t - 1) * 2048;
                #pragma unroll
                for (int nb = 0; nb < 4; ++nb) {
                    const int col = nb * 8 + 2 * lc;
                    *(float2*)(gw + (mw + lr) * 32 + col)     = make_float2(c2[nb][0], c2[nb][1]);
                    *(float2*)(gw + (mw + 8 + lr) * 32 + col) = make_float2(c2[nb][2], c2[nb][3]);
                }
            }
        }

        if (l < 3) {
            // tail: gih_{l+1}[T-1] from h_l(T-1)
            if (tid == 0) poll_ge(&bars[l * TT + TT - 1], GRP);
            __syncthreads();
            {   // all 8 warps load B(T-1) into slot 0 (4 rows each)
                u32* dhi = sm + OFF_B;
                u32* dlo = dhi + SZ_B;
                #pragma unroll
                for (int r = 0; r < 4; ++r) {
                    const int bbr = 4 * wid + r;
                    const size_t gi = ((size_t)(TT - 1) * BB + b0 + bbr) * 128 + lane * 4;
                    const uint4 vh = *(const uint4*)(outhi + gi);
                    const uint4 vl = *(const uint4*)(outlo + gi);
                    *(uint4*)(dhi + bbr * BSB + lane * 4) = vh;
                    *(uint4*)(dlo + bbr * BSB + lane * 4) = vl;
                }
            }
            __syncthreads();
            if (!comp) {
                float c2[4][4];
                const float bn0 = bsn[mw + lr], bn1 = bsn[mw + 8 + lr];
                #pragma unroll
                for (int nb = 0; nb < 4; ++nb) {
                    c2[nb][0] = bn0; c2[nb][1] = bn0; c2[nb][2] = bn1; c2[nb][3] = bn1;
                }
                const u32 f0 = bf[0][0], f1 = bf[0][1];
                #pragma unroll
                for (int kk = 0; kk < 16; ++kk) {
                    u32 pa[4], qa[4], bh[8], bl[8];
                    ldsm4(pa[0], pa[1], pa[2], pa[3], aIHhi + kk * 32);
                    ldsm4(qa[0], qa[1], qa[2], qa[3], aIHlo + kk * 32);
                    ldsm4(bh[0], bh[1], bh[2], bh[3], f0 + kk * 32);
                    ldsm4(bh[4], bh[5], bh[6], bh[7], f1 + kk * 32);
                    ldsm4(bl[0], bl[1], bl[2], bl[3], f0 + loD + kk * 32);
                    ldsm4(bl[4], bl[5], bl[6], bl[7], f1 + loD + kk * 32);
                    mma4(c2[0], pa, bh[0], bh[2]);
                    mma4(c2[1], pa, bh[1], bh[3]);
                    mma4(c2[2], pa, bh[4], bh[6]);
                    mma4(c2[3], pa, bh[5], bh[7]);
                    mma4(c2[0], pa, bl[0], bl[2]);
                    mma4(c2[1], pa, bl[1], bl[3]);
                    mma4(c2[2], pa, bl[4], bl[6]);
                    mma4(c2[3], pa, bl[5], bl[7]);
                    mma4(c2[0], qa, bh[0], bh[2]);
                    mma4(c2[1], qa, bh[1], bh[3]);
                    mma4(c2[2], qa, bh[4], bh[6]);
                    mma4(c2[3], qa, bh[5], bh[7]);
                }
                float* gw = gG0 + (size_t)(TT - 1) * 2048;
                #pragma unroll
                for (int nb = 0; nb < 4; ++nb) {
                    const int col = nb * 8 + 2 * lc;
                    *(float2*)(gw + (mw + lr) * 32 + col)     = make_float2(c2[nb][0], c2[nb][1]);
                    *(float2*)(gw + (mw + 8 + lr) * 32 + col) = make_float2(c2[nb][2], c2[nb][3]);
                }
            }
            __syncthreads();
            // stage next layer weights
            load_W(p.Whh[l + 1], j0, sAhhHi, sAhhLo);
            if (l + 2 < LL) {
                load_W(p.Wih[l + 2], j0, sAihHi, sAihLo);
                if (tid < 64) {
                    const int row = (tid >> 4) * HH + j0 + (tid & 15);
                    bsn[tid] = p.bih[l + 2][row] + p.bhh[l + 2][row];
                }
            }
            __syncthreads();
            if (comp) {
                #pragma unroll
                for (int kk = 0; kk < 16; ++kk) {
                    ldsm4(Ah[kk][0], Ah[kk][1], Ah[kk][2], Ah[kk][3], aHHhi + kk * 32);
                    ldsm4(Al[kk][0], Al[kk][1], Al[kk][2], Al[kk][3], aHHlo + kk * 32);
                }
            }
        }
    }

    // signal completion
    __syncthreads();
    if (tid == 0) arrive1(&g_fin);

    // block 0: wait for everyone, FC on h_3(T-1), reset barrier state
    if (bid == 0) {
        if (tid == 0) poll_ge(&g_fin, NBLK);
        __syncthreads();

        const int b = tid;
        float acc = p.fcb[0];
        const u32* bh = g_hBhi + ((size_t)(TT - 1) * BB + b) * 128;
        const u32* bl = g_hBlo + ((size_t)(TT - 1) * BB + b) * 128;
        #pragma unroll 4
        for (int k2 = 0; k2 < 128; ++k2) {
            const u32 hw = bh[k2];
            const u32 lw = bl[k2];
            const __nv_bfloat162 h2 = *reinterpret_cast<const __nv_bfloat162*>(&hw);
            const __nv_bfloat162 l2 = *reinterpret_cast<const __nv_bfloat162*>(&lw);
            const float h0 = __bfloat162float(h2.x) + __bfloat162float(l2.x);
            const float h1 = __bfloat162float(h2.y) + __bfloat162float(l2.y);
            const float2 w = *(const float2*)(p.fcW + 2 * k2);
            acc = fmaf(w.x, h0, fmaf(w.y, h1, acc));
        }
        p.out[b] = acc;

        for (int i = tid; i < 8 * LL * TT; i += NTHR) g_bar[i] = 0;
        if (tid == 0) g_fin = 0;
        __threadfence();
    }
}

extern "C" void kernel_launch(void* const* d_in, const int* in_sizes, int n_in,
                              void* d_out, int out_size) {
    (void)in_sizes; (void)n_in; (void)out_size;
    Params p;
    p.x = (const float*)d_in[0];
    for (int l = 0; l < LL; ++l) {
        p.Wih[l] = (const float*)d_in[1 + 4 * l];
        p.Whh[l] = (const float*)d_in[2 + 4 * l];
        p.bih[l] = (const float*)d_in[3 + 4 * l];
        p.bhh[l] = (const float*)d_in[4 + 4 * l];
    }
    p.fcW = (const float*)d_in[17];
    p.fcb = (const float*)d_in[18];
    p.out = (float*)d_out;

    cudaFuncSetAttribute(lstm_ws, cudaFuncAttributeMaxDynamicSharedMemorySize, SMEM_BYTES);
    lstm_ws<<<NBLK, NTHR, SMEM_BYTES>>>(p);
}

// round 10
// speedup vs baseline: 1.2685x; 1.2685x over previous
#include <cuda_runtime.h>
#include <cuda_bf16.h>
#include <math.h>

typedef unsigned int u32;

#define BB 256
#define TT 512
#define HH 256
#define LL 4
#define NBLK 128
#define NTHR 256

#define ALS 260            // A row stride (words): 256 k2 (concat K=512) + 4 pad
#define BSS 36             // B slot row stride (words): 32 k2 (chunk K=64) + 4 pad
#define GS2 132            // gates row stride (n=128 + 4)

#define SZ_AH (64 * ALS)       // 16640 words per A half (hi or lo)
#define SZ_BSLOT 4608          // 128 rows * 36 (one hi or lo slot)
#define OFF_AH 0
#define OFF_AL SZ_AH
#define OFF_B  (2 * SZ_AH)                  // 4 slots: s0hi, s0lo, s1hi, s1lo
#define OFF_G  OFF_B                        // gates alias slot0 (needs 8448 <= 9216 words)
#define OFF_BS (OFF_B + 4 * SZ_BSLOT)       // bias [64]
#define OFF_WX (OFF_BS + 64)                // layer-0 rank-1 weight [64]
#define OFF_XS (OFF_WX + 64)                // layer-0 x tile [128]
#define SMEM_WORDS (OFF_XS + 128)           // 51968 words
#define SMEM_BYTES (SMEM_WORDS * 4)         // ~208 KB

// ---------------- device scratch ----------------
// h per layer, batch-major packed bf16 pairs: word (t, b, k2) = {h[2k2], h[2k2+1]}
__device__ __align__(128) u32 g_hHi[LL][(size_t)TT * BB * 128];
__device__ __align__(128) u32 g_hLo[LL][(size_t)TT * BB * 128];
__device__ unsigned g_bar[LL * 2 * TT];    // [l][nb][t], target 16 arrivals
__device__ unsigned g_fin;

struct Params {
    const float* x;
    const float* Wih[LL];
    const float* Whh[LL];
    const float* bih[LL];
    const float* bhh[LL];
    const float* fcW;
    const float* fcb;
    float* out;
};

// ---------------- helpers ----------------
__device__ __forceinline__ float sigf(float v) {
    return __fdividef(1.0f, 1.0f + __expf(-v));
}
__device__ __forceinline__ float tanhfast(float v) {
    return 1.0f - __fdividef(2.0f, __expf(2.0f * v) + 1.0f);
}

__device__ __forceinline__ void split_pack(float x, float y, u32& hi, u32& lo) {
    __nv_bfloat162 h2, l2;
    h2.x = __float2bfloat16_rn(x);
    h2.y = __float2bfloat16_rn(y);
    l2.x = __float2bfloat16_rn(x - __bfloat162float(h2.x));
    l2.y = __float2bfloat16_rn(y - __bfloat162float(h2.y));
    hi = *reinterpret_cast<u32*>(&h2);
    lo = *reinterpret_cast<u32*>(&l2);
}

__device__ __forceinline__ void mma16816(float c[4], const u32 a[4], u32 b0, u32 b1) {
    asm("mma.sync.aligned.m16n8k16.row.col.f32.bf16.bf16.f32 "
        "{%0,%1,%2,%3}, {%4,%5,%6,%7}, {%8,%9}, {%0,%1,%2,%3};"
        : "+f"(c[0]), "+f"(c[1]), "+f"(c[2]), "+f"(c[3])
        : "r"(a[0]), "r"(a[1]), "r"(a[2]), "r"(a[3]), "r"(b0), "r"(b1));
}

__device__ __forceinline__ void ldsm4(u32* r, u32 addr) {
    asm volatile("ldmatrix.sync.aligned.m8n8.x4.shared.b16 {%0,%1,%2,%3}, [%4];"
                 : "=r"(r[0]), "=r"(r[1]), "=r"(r[2]), "=r"(r[3]) : "r"(addr));
}

__device__ __forceinline__ void poll_ge(unsigned* p, unsigned target) {
    unsigned v;
    asm volatile("ld.acquire.gpu.global.u32 %0, [%1];" : "=r"(v) : "l"(p) : "memory");
    while (v < target) {
        __nanosleep(32);
        asm volatile("ld.acquire.gpu.global.u32 %0, [%1];" : "=r"(v) : "l"(p) : "memory");
    }
}
__device__ __forceinline__ void arrive1(unsigned* p) {
    asm volatile("red.release.gpu.global.add.u32 [%0], %1;" :: "l"(p), "r"(1u) : "memory");
}

__device__ __forceinline__ void cpa16(u32 saddr, const u32* g) {
    asm volatile("cp.async.cg.shared.global [%0], [%1], 16;" :: "r"(saddr), "l"(g) : "memory");
}

// stage one 64x256 weight slice (rows m = g*16+jl -> global g*HH+j0+jl) into A smem at k2 col offset co
__device__ __forceinline__ void stage_W(const float* __restrict__ W, int j0, int co,
                                        u32* __restrict__ sh, u32* __restrict__ sl) {
    for (int i = threadIdx.x; i < 64 * 128; i += NTHR) {
        const int m = i >> 7;
        const int k2 = i & 127;
        const int row = (m >> 4) * HH + j0 + (m & 15);
        const float2 w = *(const float2*)(W + (size_t)row * HH + 2 * k2);
        split_pack(w.x, w.y, sh[m * ALS + co + k2], sl[m * ALS + co + k2]);
    }
}

// issue cp.async loads for one k-chunk into slot (c&1)
__device__ __forceinline__ void issue_chunk(int c, int t, int b0, u32 smb,
                                            const u32* __restrict__ inHi, const u32* __restrict__ inLo,
                                            const u32* __restrict__ recHi, const u32* __restrict__ recLo) {
    const u32* srcHi;
    const u32* srcLo;
    size_t base;
    if (c < 4) {
        srcHi = inHi; srcLo = inLo;
        base = ((size_t)t * BB + b0) * 128 + c * 32;
    } else {
        srcHi = recHi; srcLo = recLo;
        base = ((size_t)(t - 1) * BB + b0) * 128 + (c - 4) * 32;
    }
    const int s = c & 1;
    const u32 dhi = smb + (OFF_B + s * 2 * SZ_BSLOT) * 4;
    const u32 dlo = dhi + SZ_BSLOT * 4;
    #pragma unroll
    for (int i = 0; i < 4; ++i) {
        const int idx = threadIdx.x + i * NTHR;
        const int row = idx >> 3;
        const int seg = idx & 7;
        const size_t g = base + (size_t)row * 128 + seg * 4;
        const u32 so = (u32)(row * BSS + seg * 4) * 4;
        cpa16(dhi + so, srcHi + g);
        cpa16(dlo + so, srcLo + g);
    }
    asm volatile("cp.async.commit_group;" ::: "memory");
}

// ---------------- kernel ----------------
__global__ void __launch_bounds__(NTHR, 1) lstm_wave(Params p) {
    extern __shared__ u32 sm[];
    float* gsm = (float*)(sm + OFF_G);
    float* bs  = (float*)(sm + OFF_BS);
    float* wxs = (float*)(sm + OFF_WX);
    float* xs  = (float*)(sm + OFF_XS);

    const int tid  = threadIdx.x;
    const int bid  = blockIdx.x;
    const int l    = bid >> 5;           // layer 0..3
    const int nb   = (bid >> 4) & 1;     // batch half
    const int jt   = bid & 15;           // hidden tile (16 units)
    const int j0   = jt * 16;
    const int b0   = nb * 128;

    const int wid  = tid >> 5;
    const int lane = tid & 31;
    const int lr   = lane >> 2;
    const int lc   = lane & 3;
    const int mh   = wid & 1;            // m-half (32 rows)
    const int nqq  = (wid >> 1) & 3;     // n-quarter (32 cols)

    const int lrow8 = ((lane >> 3) & 1) * 8 + (lane & 7);
    const int colq  = (lane >> 4) * 4;
    const u32 smb   = (u32)__cvta_generic_to_shared(sm);
    const u32 aAh   = smb + (u32)(OFF_AH + (mh * 32 + lrow8) * ALS + colq) * 4;
    const u32 aAl   = smb + (u32)(OFF_AL + (mh * 32 + lrow8) * ALS + colq) * 4;
    const u32 ASTEP = 16 * ALS * 4;      // m16 frag step within A
    u32 bB[2];
    #pragma unroll
    for (int s = 0; s < 2; ++s)
        bB[s] = smb + (u32)(OFF_B + s * 2 * SZ_BSLOT + (nqq * 32 + lrow8) * BSS + colq) * 4;
    const u32 BLO  = SZ_BSLOT * 4;       // hi -> lo
    const u32 BGRP = 16 * BSS * 4;       // second n16 group

    // stage weights once (this block serves layer l forever)
    if (l > 0) stage_W(p.Wih[l], j0, 0, sm + OFF_AH, sm + OFF_AL);
    stage_W(p.Whh[l], j0, 128, sm + OFF_AH, sm + OFF_AL);
    if (tid < 64) {
        const int row = (tid >> 4) * HH + j0 + (tid & 15);
        bs[tid] = p.bih[l][row] + p.bhh[l][row];
        if (l == 0) wxs[tid] = p.Wih[0][row];   // W_ih0 is [4H,1]
    }
    __syncthreads();

    unsigned* barsIn  = (l > 0) ? (g_bar + ((l - 1) * 2 + nb) * TT) : nullptr;
    unsigned* barsOwn = g_bar + (l * 2 + nb) * TT;
    u32* outHi = g_hHi[l];
    u32* outLo = g_hLo[l];
    const u32* inHi = (l > 0) ? g_hHi[l - 1] : nullptr;
    const u32* inLo = (l > 0) ? g_hLo[l - 1] : nullptr;

    // elementwise ownership: batch col eb, 4 hidden-pairs starting jq
    const int eb = tid & 127;
    const int jq = (tid >> 7) * 4;
    float cc[8];
    #pragma unroll
    for (int i = 0; i < 8; ++i) cc[i] = 0.f;

    const int cbeg = (l == 0) ? 4 : 0;
    const int mf0 = mh * 32;
    const int mf1 = mh * 32 + 16;

    for (int t = 0; t < TT; ++t) {
        if (l == 0 && tid < 128) xs[tid] = p.x[(size_t)(b0 + tid) * TT + t];

        if (tid == 0) {
            if (l > 0) poll_ge(&barsIn[t], 16);
            if (t > 0) poll_ge(&barsOwn[t - 1], 16);
        }
        __syncthreads();

        const int cend = (t == 0) ? 4 : 8;   // l==0,t==0: cbeg=4,cend=4 -> no chunks

        if (cbeg < cend) issue_chunk(cbeg, t, b0, smb, inHi, inLo, outHi, outLo);

        // init accumulators: bias (+ rank-1 x for layer 0)
        float c[2][4][4];
        {
            const float b00 = bs[mf0 + lr], b01 = bs[mf0 + 8 + lr];
            const float b10 = bs[mf1 + lr], b11 = bs[mf1 + 8 + lr];
            #pragma unroll
            for (int ni = 0; ni < 4; ++ni) {
                c[0][ni][0] = b00; c[0][ni][1] = b00; c[0][ni][2] = b01; c[0][ni][3] = b01;
                c[1][ni][0] = b10; c[1][ni][1] = b10; c[1][ni][2] = b11; c[1][ni][3] = b11;
            }
            if (l == 0) {
                const float w00 = wxs[mf0 + lr], w01 = wxs[mf0 + 8 + lr];
                const float w10 = wxs[mf1 + lr], w11 = wxs[mf1 + 8 + lr];
                #pragma unroll
                for (int ni = 0; ni < 4; ++ni) {
                    const int col = nqq * 32 + ni * 8 + 2 * lc;
                    const float xv0 = xs[col], xv1 = xs[col + 1];
                    c[0][ni][0] = fmaf(w00, xv0, c[0][ni][0]);
                    c[0][ni][1] = fmaf(w00, xv1, c[0][ni][1]);
                    c[0][ni][2] = fmaf(w01, xv0, c[0][ni][2]);
                    c[0][ni][3] = fmaf(w01, xv1, c[0][ni][3]);
                    c[1][ni][0] = fmaf(w10, xv0, c[1][ni][0]);
                    c[1][ni][1] = fmaf(w10, xv1, c[1][ni][1]);
                    c[1][ni][2] = fmaf(w11, xv0, c[1][ni][2]);
                    c[1][ni][3] = fmaf(w11, xv1, c[1][ni][3]);
                }
            }
        }

        for (int ch = cbeg; ch < cend; ++ch) {
            asm volatile("cp.async.wait_group 0;" ::: "memory");
            __syncthreads();                       // chunk ch in smem; prev slot reads done
            if (ch + 1 < cend)
                issue_chunk(ch + 1, t, b0, smb, inHi, inLo, outHi, outLo);

            const u32 bs0 = bB[ch & 1];
            #pragma unroll
            for (int q = 0; q < 4; ++q) {
                const int kk = ch * 4 + q;
                u32 A0[4], A1[4], L0[4], L1[4], H0[4], H1[4], Q0[4], Q1[4];
                ldsm4(A0, aAh + kk * 32);
                ldsm4(A1, aAh + ASTEP + kk * 32);
                ldsm4(L0, aAl + kk * 32);
                ldsm4(L1, aAl + ASTEP + kk * 32);
                ldsm4(H0, bs0 + q * 32);
                ldsm4(H1, bs0 + BGRP + q * 32);
                ldsm4(Q0, bs0 + BLO + q * 32);
                ldsm4(Q1, bs0 + BLO + BGRP + q * 32);
                // pass 1: Ah x Bh
                mma16816(c[0][0], A0, H0[0], H0[2]);
                mma16816(c[0][1], A0, H0[1], H0[3]);
                mma16816(c[0][2], A0, H1[0], H1[2]);
                mma16816(c[0][3], A0, H1[1], H1[3]);
                mma16816(c[1][0], A1, H0[0], H0[2]);
                mma16816(c[1][1], A1, H0[1], H0[3]);
                mma16816(c[1][2], A1, H1[0], H1[2]);
                mma16816(c[1][3], A1, H1[1], H1[3]);
                // pass 2: Ah x Bl
                mma16816(c[0][0], A0, Q0[0], Q0[2]);
                mma16816(c[0][1], A0, Q0[1], Q0[3]);
                mma16816(c[0][2], A0, Q1[0], Q1[2]);
                mma16816(c[0][3], A0, Q1[1], Q1[3]);
                mma16816(c[1][0], A1, Q0[0], Q0[2]);
                mma16816(c[1][1], A1, Q0[1], Q0[3]);
                mma16816(c[1][2], A1, Q1[0], Q1[2]);
                mma16816(c[1][3], A1, Q1[1], Q1[3]);
                // pass 3: Al x Bh
                mma16816(c[0][0], L0, H0[0], H0[2]);
                mma16816(c[0][1], L0, H0[1], H0[3]);
                mma16816(c[0][2], L0, H1[0], H1[2]);
                mma16816(c[0][3], L0, H1[1], H1[3]);
                mma16816(c[1][0], L1, H0[0], H0[2]);
                mma16816(c[1][1], L1, H0[1], H0[3]);
                mma16816(c[1][2], L1, H1[0], H1[2]);
                mma16816(c[1][3], L1, H1[1], H1[3]);
            }
        }

        // gates -> smem (aliases slot0; last mma read slot1, slot0 readers synced)
        #pragma unroll
        for (int mi = 0; mi < 2; ++mi) {
            const int mf = mh * 32 + mi * 16;
            #pragma unroll
            for (int ni = 0; ni < 4; ++ni) {
                const int col = nqq * 32 + ni * 8 + 2 * lc;
                *(float2*)(gsm + (mf + lr) * GS2 + col)     = make_float2(c[mi][ni][0], c[mi][ni][1]);
                *(float2*)(gsm + (mf + 8 + lr) * GS2 + col) = make_float2(c[mi][ni][2], c[mi][ni][3]);
            }
        }
        __syncthreads();

        // elementwise: 4 hidden-pairs x 1 batch col per thread
        {
            u32 hw[4], lw[4];
            #pragma unroll
            for (int jj = 0; jj < 4; ++jj) {
                const int jl0 = 2 * (jq + jj), jl1 = jl0 + 1;
                const float ig0 = gsm[jl0 * GS2 + eb];
                const float fg0 = gsm[(16 + jl0) * GS2 + eb];
                const float gg0 = gsm[(32 + jl0) * GS2 + eb];
                const float og0 = gsm[(48 + jl0) * GS2 + eb];
                const float ig1 = gsm[jl1 * GS2 + eb];
                const float fg1 = gsm[(16 + jl1) * GS2 + eb];
                const float gg1 = gsm[(32 + jl1) * GS2 + eb];
                const float og1 = gsm[(48 + jl1) * GS2 + eb];

                cc[2 * jj]     = sigf(fg0) * cc[2 * jj]     + sigf(ig0) * tanhfast(gg0);
                cc[2 * jj + 1] = sigf(fg1) * cc[2 * jj + 1] + sigf(ig1) * tanhfast(gg1);
                const float h0 = sigf(og0) * tanhfast(cc[2 * jj]);
                const float h1 = sigf(og1) * tanhfast(cc[2 * jj + 1]);
                split_pack(h0, h1, hw[jj], lw[jj]);
            }
            const size_t wi = ((size_t)t * BB + b0 + eb) * 128 + jt * 8 + jq;
            *(uint4*)(outHi + wi) = make_uint4(hw[0], hw[1], hw[2], hw[3]);
            *(uint4*)(outLo + wi) = make_uint4(lw[0], lw[1], lw[2], lw[3]);
        }
        __syncthreads();
        if (tid == 0) arrive1(&barsOwn[t]);
    }

    // completion + final FC
    __syncthreads();
    if (tid == 0) arrive1(&g_fin);

    if (bid == 0) {
        if (tid == 0) poll_ge(&g_fin, NBLK);
        __syncthreads();

        const int b = tid;   // 256 threads = 256 batch rows
        float acc = p.fcb[0];
        const u32* bh = g_hHi[3] + ((size_t)(TT - 1) * BB + b) * 128;
        const u32* bl = g_hLo[3] + ((size_t)(TT - 1) * BB + b) * 128;
        #pragma unroll 4
        for (int k2 = 0; k2 < 128; ++k2) {
            const u32 hwv = bh[k2];
            const u32 lwv = bl[k2];
            const __nv_bfloat162 h2 = *reinterpret_cast<const __nv_bfloat162*>(&hwv);
            const __nv_bfloat162 l2 = *reinterpret_cast<const __nv_bfloat162*>(&lwv);
            const float h0 = __bfloat162float(h2.x) + __bfloat162float(l2.x);
            const float h1 = __bfloat162float(h2.y) + __bfloat162float(l2.y);
            const float2 w = *(const float2*)(p.fcW + 2 * k2);
            acc = fmaf(w.x, h0, fmaf(w.y, h1, acc));
        }
        p.out[b] = acc;

        for (int i = tid; i < LL * 2 * TT; i += NTHR) g_bar[i] = 0;
        if (tid == 0) g_fin = 0;
        __threadfence();
    }
}

extern "C" void kernel_launch(void* const* d_in, const int* in_sizes, int n_in,
                              void* d_out, int out_size) {
    (void)in_sizes; (void)n_in; (void)out_size;
    Params p;
    p.x = (const float*)d_in[0];
    for (int l = 0; l < LL; ++l) {
        p.Wih[l] = (const float*)d_in[1 + 4 * l];
        p.Whh[l] = (const float*)d_in[2 + 4 * l];
        p.bih[l] = (const float*)d_in[3 + 4 * l];
        p.bhh[l] = (const float*)d_in[4 + 4 * l];
    }
    p.fcW = (const float*)d_in[17];
    p.fcb = (const float*)d_in[18];
    p.out = (float*)d_out;

    cudaFuncSetAttribute(lstm_wave, cudaFuncAttributeMaxDynamicSharedMemorySize, SMEM_BYTES);
    lstm_wave<<<NBLK, NTHR, SMEM_BYTES>>>(p);
}

// round 11
// speedup vs baseline: 1.3551x; 1.0683x over previous
#include <cuda_runtime.h>
#include <cuda_bf16.h>
#include <math.h>

typedef unsigned int u32;

#define BB 256
#define TT 512
#define HH 256
#define LL 4
#define NBLK 128
#define NTHR 512

#define ALS 260            // A row stride (words): 256 k2 (concat K=512) + 4 pad
#define BSS 36             // B slot row stride (words): 32 k2 (chunk K=64) + 4 pad
#define GS2 132            // gates row stride (n=128 + 4)

#define SZ_AH (64 * ALS)       // 16640 words per A half (hi or lo)
#define SZ_BSLOT 4608          // 128 rows * 36 (one hi or lo slot)
#define OFF_AH 0
#define OFF_AL SZ_AH
#define OFF_B  (2 * SZ_AH)                  // 4 slots: s0hi, s0lo, s1hi, s1lo
#define OFF_G  OFF_B                        // gates alias slot0-pair (8448 <= 9216 words)
#define OFF_BS (OFF_B + 4 * SZ_BSLOT)       // bias [64]
#define OFF_WX (OFF_BS + 64)                // layer-0 rank-1 weight [64]
#define OFF_XS (OFF_WX + 64)                // layer-0 x tile [128]
#define SMEM_WORDS (OFF_XS + 128)           // 51968 words
#define SMEM_BYTES (SMEM_WORDS * 4)         // ~208 KB

// ---------------- device scratch ----------------
__device__ __align__(128) u32 g_hHi[LL][(size_t)TT * BB * 128];
__device__ __align__(128) u32 g_hLo[LL][(size_t)TT * BB * 128];
__device__ unsigned g_bar[LL * 2 * TT];    // [l][nb][t], target 16 arrivals
__device__ unsigned g_fin;

struct Params {
    const float* x;
    const float* Wih[LL];
    const float* Whh[LL];
    const float* bih[LL];
    const float* bhh[LL];
    const float* fcW;
    const float* fcb;
    float* out;
};

// ---------------- helpers ----------------
__device__ __forceinline__ float sigf(float v) {
    return __fdividef(1.0f, 1.0f + __expf(-v));
}
__device__ __forceinline__ float tanhfast(float v) {
    return 1.0f - __fdividef(2.0f, __expf(2.0f * v) + 1.0f);
}

__device__ __forceinline__ void split_pack(float x, float y, u32& hi, u32& lo) {
    __nv_bfloat162 h2, l2;
    h2.x = __float2bfloat16_rn(x);
    h2.y = __float2bfloat16_rn(y);
    l2.x = __float2bfloat16_rn(x - __bfloat162float(h2.x));
    l2.y = __float2bfloat16_rn(y - __bfloat162float(h2.y));
    hi = *reinterpret_cast<u32*>(&h2);
    lo = *reinterpret_cast<u32*>(&l2);
}

__device__ __forceinline__ void mma16816(float c[4], const u32 a[4], u32 b0, u32 b1) {
    asm("mma.sync.aligned.m16n8k16.row.col.f32.bf16.bf16.f32 "
        "{%0,%1,%2,%3}, {%4,%5,%6,%7}, {%8,%9}, {%0,%1,%2,%3};"
        : "+f"(c[0]), "+f"(c[1]), "+f"(c[2]), "+f"(c[3])
        : "r"(a[0]), "r"(a[1]), "r"(a[2]), "r"(a[3]), "r"(b0), "r"(b1));
}

__device__ __forceinline__ void ldsm4(u32* r, u32 addr) {
    asm volatile("ldmatrix.sync.aligned.m8n8.x4.shared.b16 {%0,%1,%2,%3}, [%4];"
                 : "=r"(r[0]), "=r"(r[1]), "=r"(r[2]), "=r"(r[3]) : "r"(addr));
}

__device__ __forceinline__ void poll_ge(unsigned* p, unsigned target) {
    unsigned v;
    asm volatile("ld.acquire.gpu.global.u32 %0, [%1];" : "=r"(v) : "l"(p) : "memory");
    while (v < target) {
        __nanosleep(32);
        asm volatile("ld.acquire.gpu.global.u32 %0, [%1];" : "=r"(v) : "l"(p) : "memory");
    }
}
__device__ __forceinline__ void arrive1(unsigned* p) {
    asm volatile("red.release.gpu.global.add.u32 [%0], %1;" :: "l"(p), "r"(1u) : "memory");
}

__device__ __forceinline__ void cpa16(u32 saddr, const u32* g) {
    asm volatile("cp.async.cg.shared.global [%0], [%1], 16;" :: "r"(saddr), "l"(g) : "memory");
}

// stage one 64x256 weight slice into A smem at k2 col offset co
__device__ __forceinline__ void stage_W(const float* __restrict__ W, int j0, int co,
                                        u32* __restrict__ sh, u32* __restrict__ sl) {
    for (int i = threadIdx.x; i < 64 * 128; i += NTHR) {
        const int m = i >> 7;
        const int k2 = i & 127;
        const int row = (m >> 4) * HH + j0 + (m & 15);
        const float2 w = *(const float2*)(W + (size_t)row * HH + 2 * k2);
        split_pack(w.x, w.y, sh[m * ALS + co + k2], sl[m * ALS + co + k2]);
    }
}

// issue cp.async loads for one k-chunk into slot (c&1)
__device__ __forceinline__ void issue_chunk(int c, int t, int b0, u32 smb,
                                            const u32* __restrict__ inHi, const u32* __restrict__ inLo,
                                            const u32* __restrict__ recHi, const u32* __restrict__ recLo) {
    const u32* srcHi;
    const u32* srcLo;
    size_t base;
    if (c < 4) {
        srcHi = inHi; srcLo = inLo;
        base = ((size_t)t * BB + b0) * 128 + c * 32;
    } else {
        srcHi = recHi; srcLo = recLo;
        base = ((size_t)(t - 1) * BB + b0) * 128 + (c - 4) * 32;
    }
    const int s = c & 1;
    const u32 dhi = smb + (OFF_B + s * 2 * SZ_BSLOT) * 4;
    const u32 dlo = dhi + SZ_BSLOT * 4;
    #pragma unroll
    for (int i = 0; i < 2; ++i) {
        const int idx = threadIdx.x + i * NTHR;
        const int row = idx >> 3;
        const int seg = idx & 7;
        const size_t g = base + (size_t)row * 128 + seg * 4;
        const u32 so = (u32)(row * BSS + seg * 4) * 4;
        cpa16(dhi + so, srcHi + g);
        cpa16(dlo + so, srcLo + g);
    }
    asm volatile("cp.async.commit_group;" ::: "memory");
}

// ---------------- kernel ----------------
__global__ void __launch_bounds__(NTHR, 1) lstm_wave2(Params p) {
    extern __shared__ u32 sm[];
    float* gsm = (float*)(sm + OFF_G);
    float* bs  = (float*)(sm + OFF_BS);
    float* wxs = (float*)(sm + OFF_WX);
    float* xs  = (float*)(sm + OFF_XS);

    const int tid  = threadIdx.x;
    const int bid  = blockIdx.x;
    const int l    = bid >> 5;           // layer 0..3
    const int nb   = (bid >> 4) & 1;     // batch half
    const int jt   = bid & 15;           // hidden tile (16 units)
    const int j0   = jt * 16;
    const int b0   = nb * 128;

    const int wid  = tid >> 5;
    const int lane = tid & 31;
    const int lr   = lane >> 2;
    const int lc   = lane & 3;
    const int mh   = wid & 1;            // m-half (32 rows)
    const int ne   = wid >> 1;           // n-eighth (16 cols), 0..7

    const int lrow8 = ((lane >> 3) & 1) * 8 + (lane & 7);
    const int colq  = (lane >> 4) * 4;
    const u32 smb   = (u32)__cvta_generic_to_shared(sm);
    const u32 aAh   = smb + (u32)(OFF_AH + (mh * 32 + lrow8) * ALS + colq) * 4;
    const u32 aAl   = smb + (u32)(OFF_AL + (mh * 32 + lrow8) * ALS + colq) * 4;
    const u32 ASTEP = 16 * ALS * 4;      // m16 frag step within A
    u32 bB[2];
    #pragma unroll
    for (int s = 0; s < 2; ++s)
        bB[s] = smb + (u32)(OFF_B + s * 2 * SZ_BSLOT + (ne * 16 + lrow8) * BSS + colq) * 4;
    const u32 BLO  = SZ_BSLOT * 4;       // hi -> lo within slot

    // stage weights once (this block serves layer l forever)
    if (l > 0) stage_W(p.Wih[l], j0, 0, sm + OFF_AH, sm + OFF_AL);
    stage_W(p.Whh[l], j0, 128, sm + OFF_AH, sm + OFF_AL);
    if (tid < 64) {
        const int row = (tid >> 4) * HH + j0 + (tid & 15);
        bs[tid] = p.bih[l][row] + p.bhh[l][row];
        if (l == 0) wxs[tid] = p.Wih[0][row];   // W_ih0 is [4H,1]
    }
    __syncthreads();

    unsigned* barsIn  = (l > 0) ? (g_bar + ((l - 1) * 2 + nb) * TT) : nullptr;
    unsigned* barsOwn = g_bar + (l * 2 + nb) * TT;
    u32* outHi = g_hHi[l];
    u32* outLo = g_hLo[l];
    const u32* inHi = (l > 0) ? g_hHi[l - 1] : nullptr;
    const u32* inLo = (l > 0) ? g_hLo[l - 1] : nullptr;

    // elementwise ownership: batch col eb, 2 hidden-pairs starting jq
    const int eb = tid & 127;
    const int jq = (tid >> 7) * 2;       // 0,2,4,6
    float cc[4];
    #pragma unroll
    for (int i = 0; i < 4; ++i) cc[i] = 0.f;

    const int mf0 = mh * 32;
    const int mf1 = mh * 32 + 16;

    for (int t = 0; t < TT; ++t) {
        if (l == 0 && tid < 128) xs[tid] = p.x[(size_t)(b0 + tid) * TT + t];

        // accumulators: bias
        float c[2][2][4];
        {
            const float b00 = bs[mf0 + lr], b01 = bs[mf0 + 8 + lr];
            const float b10 = bs[mf1 + lr], b11 = bs[mf1 + 8 + lr];
            #pragma unroll
            for (int ni = 0; ni < 2; ++ni) {
                c[0][ni][0] = b00; c[0][ni][1] = b00; c[0][ni][2] = b01; c[0][ni][3] = b01;
                c[1][ni][0] = b10; c[1][ni][1] = b10; c[1][ni][2] = b11; c[1][ni][3] = b11;
            }
        }

        if (l > 0) {
            // -------- input half: chunks 0..3, gated by layer l-1 --------
            if (tid == 0) poll_ge(&barsIn[t], 16);
            __syncthreads();
            issue_chunk(0, t, b0, smb, inHi, inLo, outHi, outLo);
            for (int ch = 0; ch < 4; ++ch) {
                asm volatile("cp.async.wait_group 0;" ::: "memory");
                __syncthreads();
                if (ch < 3) issue_chunk(ch + 1, t, b0, smb, inHi, inLo, outHi, outLo);
                // overlap the own-layer poll with in-half compute (ordered by next sync)
                if (ch == 2 && t > 0 && tid == 0) poll_ge(&barsOwn[t - 1], 16);
                if (ch == 3 && t > 0) issue_chunk(4, t, b0, smb, inHi, inLo, outHi, outLo);

                const u32 bhi = bB[ch & 1];
                #pragma unroll
                for (int q = 0; q < 4; ++q) {
                    const int kk = ch * 4 + q;
                    u32 A0[4], A1[4], L0[4], L1[4], H[4], Q[4];
                    ldsm4(A0, aAh + kk * 32);
                    ldsm4(A1, aAh + ASTEP + kk * 32);
                    ldsm4(L0, aAl + kk * 32);
                    ldsm4(L1, aAl + ASTEP + kk * 32);
                    ldsm4(H, bhi + q * 32);
                    ldsm4(Q, bhi + BLO + q * 32);
                    mma16816(c[0][0], A0, H[0], H[2]);
                    mma16816(c[0][1], A0, H[1], H[3]);
                    mma16816(c[1][0], A1, H[0], H[2]);
                    mma16816(c[1][1], A1, H[1], H[3]);
                    mma16816(c[0][0], A0, Q[0], Q[2]);
                    mma16816(c[0][1], A0, Q[1], Q[3]);
                    mma16816(c[1][0], A1, Q[0], Q[2]);
                    mma16816(c[1][1], A1, Q[1], Q[3]);
                    mma16816(c[0][0], L0, H[0], H[2]);
                    mma16816(c[0][1], L0, H[1], H[3]);
                    mma16816(c[1][0], L1, H[0], H[2]);
                    mma16816(c[1][1], L1, H[1], H[3]);
                }
            }
        } else {
            // -------- layer 0: rank-1 input term --------
            if (t > 0) {
                if (tid == 0) poll_ge(&barsOwn[t - 1], 16);
                __syncthreads();           // also publishes xs
                issue_chunk(4, t, b0, smb, inHi, inLo, outHi, outLo);
            } else {
                __syncthreads();           // publish xs
            }
            {
                const float w00 = wxs[mf0 + lr], w01 = wxs[mf0 + 8 + lr];
                const float w10 = wxs[mf1 + lr], w11 = wxs[mf1 + 8 + lr];
                #pragma unroll
                for (int ni = 0; ni < 2; ++ni) {
                    const int col = ne * 16 + ni * 8 + 2 * lc;
                    const float xv0 = xs[col], xv1 = xs[col + 1];
                    c[0][ni][0] = fmaf(w00, xv0, c[0][ni][0]);
                    c[0][ni][1] = fmaf(w00, xv1, c[0][ni][1]);
                    c[0][ni][2] = fmaf(w01, xv0, c[0][ni][2]);
                    c[0][ni][3] = fmaf(w01, xv1, c[0][ni][3]);
                    c[1][ni][0] = fmaf(w10, xv0, c[1][ni][0]);
                    c[1][ni][1] = fmaf(w10, xv1, c[1][ni][1]);
                    c[1][ni][2] = fmaf(w11, xv0, c[1][ni][2]);
                    c[1][ni][3] = fmaf(w11, xv1, c[1][ni][3]);
                }
            }
        }

        // -------- recurrent half: chunks 4..7 --------
        if (t > 0) {
            for (int ch = 4; ch < 8; ++ch) {
                asm volatile("cp.async.wait_group 0;" ::: "memory");
                __syncthreads();
                if (ch < 7) issue_chunk(ch + 1, t, b0, smb, inHi, inLo, outHi, outLo);

                const u32 bhi = bB[ch & 1];
                #pragma unroll
                for (int q = 0; q < 4; ++q) {
                    const int kk = ch * 4 + q;
                    u32 A0[4], A1[4], L0[4], L1[4], H[4], Q[4];
                    ldsm4(A0, aAh + kk * 32);
                    ldsm4(A1, aAh + ASTEP + kk * 32);
                    ldsm4(L0, aAl + kk * 32);
                    ldsm4(L1, aAl + ASTEP + kk * 32);
                    ldsm4(H, bhi + q * 32);
                    ldsm4(Q, bhi + BLO + q * 32);
                    mma16816(c[0][0], A0, H[0], H[2]);
                    mma16816(c[0][1], A0, H[1], H[3]);
                    mma16816(c[1][0], A1, H[0], H[2]);
                    mma16816(c[1][1], A1, H[1], H[3]);
                    mma16816(c[0][0], A0, Q[0], Q[2]);
                    mma16816(c[0][1], A0, Q[1], Q[3]);
                    mma16816(c[1][0], A1, Q[0], Q[2]);
                    mma16816(c[1][1], A1, Q[1], Q[3]);
                    mma16816(c[0][0], L0, H[0], H[2]);
                    mma16816(c[0][1], L0, H[1], H[3]);
                    mma16816(c[1][0], L1, H[0], H[2]);
                    mma16816(c[1][1], L1, H[1], H[3]);
                }
            }
        }

        // gates -> smem (aliases slot0-pair; safe: last chunk read slot1, slot0 readers synced)
        #pragma unroll
        for (int mi = 0; mi < 2; ++mi) {
            const int mf = mh * 32 + mi * 16;
            #pragma unroll
            for (int ni = 0; ni < 2; ++ni) {
                const int col = ne * 16 + ni * 8 + 2 * lc;
                *(float2*)(gsm + (mf + lr) * GS2 + col)     = make_float2(c[mi][ni][0], c[mi][ni][1]);
                *(float2*)(gsm + (mf + 8 + lr) * GS2 + col) = make_float2(c[mi][ni][2], c[mi][ni][3]);
            }
        }
        __syncthreads();

        // elementwise: 2 hidden-pairs x 1 batch col per thread
        {
            u32 hw[2], lw[2];
            #pragma unroll
            for (int jj = 0; jj < 2; ++jj) {
                const int jl0 = 2 * (jq + jj), jl1 = jl0 + 1;
                const float ig0 = gsm[jl0 * GS2 + eb];
                const float fg0 = gsm[(16 + jl0) * GS2 + eb];
                const float gg0 = gsm[(32 + jl0) * GS2 + eb];
                const float og0 = gsm[(48 + jl0) * GS2 + eb];
                const float ig1 = gsm[jl1 * GS2 + eb];
                const float fg1 = gsm[(16 + jl1) * GS2 + eb];
                const float gg1 = gsm[(32 + jl1) * GS2 + eb];
                const float og1 = gsm[(48 + jl1) * GS2 + eb];

                cc[2 * jj]     = sigf(fg0) * cc[2 * jj]     + sigf(ig0) * tanhfast(gg0);
                cc[2 * jj + 1] = sigf(fg1) * cc[2 * jj + 1] + sigf(ig1) * tanhfast(gg1);
                const float h0 = sigf(og0) * tanhfast(cc[2 * jj]);
                const float h1 = sigf(og1) * tanhfast(cc[2 * jj + 1]);
                split_pack(h0, h1, hw[jj], lw[jj]);
            }
            const size_t wi = ((size_t)t * BB + b0 + eb) * 128 + jt * 8 + jq;
            *(uint2*)(outHi + wi) = make_uint2(hw[0], hw[1]);
            *(uint2*)(outLo + wi) = make_uint2(lw[0], lw[1]);
        }
        __syncthreads();
        if (tid == 0) arrive1(&barsOwn[t]);
    }

    // completion + final FC
    __syncthreads();
    if (tid == 0) arrive1(&g_fin);

    if (bid == 0) {
        if (tid == 0) poll_ge(&g_fin, NBLK);
        __syncthreads();

        if (tid < BB) {
            const int b = tid;
            float acc = p.fcb[0];
            const u32* bh = g_hHi[3] + ((size_t)(TT - 1) * BB + b) * 128;
            const u32* bl = g_hLo[3] + ((size_t)(TT - 1) * BB + b) * 128;
            #pragma unroll 4
            for (int k2 = 0; k2 < 128; ++k2) {
                const u32 hwv = bh[k2];
                const u32 lwv = bl[k2];
                const __nv_bfloat162 h2 = *reinterpret_cast<const __nv_bfloat162*>(&hwv);
                const __nv_bfloat162 l2 = *reinterpret_cast<const __nv_bfloat162*>(&lwv);
                const float h0 = __bfloat162float(h2.x) + __bfloat162float(l2.x);
                const float h1 = __bfloat162float(h2.y) + __bfloat162float(l2.y);
                const float2 w = *(const float2*)(p.fcW + 2 * k2);
                acc = fmaf(w.x, h0, fmaf(w.y, h1, acc));
            }
            p.out[b] = acc;
        }

        for (int i = tid; i < LL * 2 * TT; i += NTHR) g_bar[i] = 0;
        if (tid == 0) g_fin = 0;
        __threadfence();
    }
}

extern "C" void kernel_launch(void* const* d_in, const int* in_sizes, int n_in,
                              void* d_out, int out_size) {
    (void)in_sizes; (void)n_in; (void)out_size;
    Params p;
    p.x = (const float*)d_in[0];
    for (int l = 0; l < LL; ++l) {
        p.Wih[l] = (const float*)d_in[1 + 4 * l];
        p.Whh[l] = (const float*)d_in[2 + 4 * l];
        p.bih[l] = (const float*)d_in[3 + 4 * l];
        p.bhh[l] = (const float*)d_in[4 + 4 * l];
    }
    p.fcW = (const float*)d_in[17];
    p.fcb = (const float*)d_in[18];
    p.out = (float*)d_out;

    cudaFuncSetAttribute(lstm_wave2, cudaFuncAttributeMaxDynamicSharedMemorySize, SMEM_BYTES);
    lstm_wave2<<<NBLK, NTHR, SMEM_BYTES>>>(p);
}

// round 14
// speedup vs baseline: 1.8190x; 1.3424x over previous
#include <cuda_runtime.h>
#include <cuda_fp16.h>
#include <math.h>

typedef unsigned int u32;

#define BB 256
#define TT 512
#define HH 256
#define LL 4
#define NBLK 128
#define NTHR 512

#define ALS 260            // A row stride (words): 256 k2 (concat K=512 fp16 pairs) + 4 pad
#define BSS 36             // B slot row stride (words): 32 k2 + 4 pad
#define GS2 132            // gate region row stride (n=128 + 4)

#define SZ_AH (64 * ALS)       // 16640 words per A half (hi or scaled-lo)
#define SZ_BSLOT 4608          // 128 rows * 36 words (one K=64 chunk, hi-only)
#define OFF_AH 0
#define OFF_AL SZ_AH
#define OFF_B  (2 * SZ_AH)                  // 4 chunk slots: sec0r0, sec0r1, sec1r0, sec1r1
#define OFF_G  OFF_B                        // 2 gate regions (2*8448 = 16896 <= 18432 words) alias slots
#define OFF_BS (OFF_B + 4 * SZ_BSLOT)       // bias [64]
#define OFF_WX (OFF_BS + 64)                // layer-0 rank-1 weight [64]
#define OFF_XS (OFF_WX + 64)                // layer-0 x tile [128]
#define SMEM_WORDS (OFF_XS + 128)           // 51968 words
#define SMEM_BYTES (SMEM_WORDS * 4)         // ~208 KB

#define ASTEPB (16 * ALS * 4)   // m16 frag row step in A (bytes)
#define BGRPB  (16 * BSS * 4)   // second n16 group step in B slot (bytes)

// ---------------- device scratch ----------------
// h per layer, batch-major packed fp16 pairs: word (t, b, k2) = {h[2k2], h[2k2+1]}
__device__ __align__(128) u32 g_h[LL][(size_t)TT * BB * 128];
__device__ unsigned g_bar[LL * 2 * TT];    // [l][nb][t], target 16 arrivals
__device__ unsigned g_fin;

struct Params {
    const float* x;
    const float* Wih[LL];
    const float* Whh[LL];
    const float* bih[LL];
    const float* bhh[LL];
    const float* fcW;
    const float* fcb;
    float* out;
};

// ---------------- helpers ----------------
__device__ __forceinline__ float sigf(float v) {
    return __fdividef(1.0f, 1.0f + __expf(-v));
}
__device__ __forceinline__ float tanhfast(float v) {
    return 1.0f - __fdividef(2.0f, __expf(2.0f * v) + 1.0f);
}

__device__ __forceinline__ void mma16816(float c[4], const u32 a[4], u32 b0, u32 b1) {
    asm("mma.sync.aligned.m16n8k16.row.col.f32.f16.f16.f32 "
        "{%0,%1,%2,%3}, {%4,%5,%6,%7}, {%8,%9}, {%0,%1,%2,%3};"
        : "+f"(c[0]), "+f"(c[1]), "+f"(c[2]), "+f"(c[3])
        : "r"(a[0]), "r"(a[1]), "r"(a[2]), "r"(a[3]), "r"(b0), "r"(b1));
}

__device__ __forceinline__ void ldsm4(u32* r, u32 addr) {
    asm volatile("ldmatrix.sync.aligned.m8n8.x4.shared.b16 {%0,%1,%2,%3}, [%4];"
                 : "=r"(r[0]), "=r"(r[1]), "=r"(r[2]), "=r"(r[3]) : "r"(addr));
}

__device__ __forceinline__ void poll_ge(unsigned* p, unsigned target) {
    unsigned v;
    asm volatile("ld.acquire.gpu.global.u32 %0, [%1];" : "=r"(v) : "l"(p) : "memory");
    while (v < target) {
        __nanosleep(32);
        asm volatile("ld.acquire.gpu.global.u32 %0, [%1];" : "=r"(v) : "l"(p) : "memory");
    }
}
__device__ __forceinline__ void arrive1(unsigned* p) {
    asm volatile("red.release.gpu.global.add.u32 [%0], %1;" :: "l"(p), "r"(1u) : "memory");
}

__device__ __forceinline__ void cpa16(u32 saddr, const u32* g) {
    asm volatile("cp.async.cg.shared.global [%0], [%1], 16;" :: "r"(saddr), "l"(g) : "memory");
}

// stage one 64x256 fp32 weight slice into A smem (fp16 hi + fp16 lo*256) at k2 col offset co
__device__ __forceinline__ void stage_W(const float* __restrict__ W, int j0, int co,
                                        u32* __restrict__ sh, u32* __restrict__ sl) {
    for (int i = threadIdx.x; i < 64 * 128; i += NTHR) {
        const int m = i >> 7;
        const int k2 = i & 127;
        const int row = (m >> 4) * HH + j0 + (m & 15);
        const float2 w = *(const float2*)(W + (size_t)row * HH + 2 * k2);
        const __half hx = __float2half_rn(w.x);
        const __half hy = __float2half_rn(w.y);
        const __half lx = __float2half_rn((w.x - __half2float(hx)) * 256.0f);
        const __half ly = __float2half_rn((w.y - __half2float(hy)) * 256.0f);
        __half2 h2 = __halves2half2(hx, hy);
        __half2 l2 = __halves2half2(lx, ly);
        sh[m * ALS + co + k2] = *reinterpret_cast<u32*>(&h2);
        sl[m * ALS + co + k2] = *reinterpret_cast<u32*>(&l2);
    }
}

// issue both sections' round-r chunks from srcbuf at time tsrc (one commit group)
__device__ __forceinline__ void issue_pair(const u32* __restrict__ srcbuf, int tsrc, int r,
                                           int b0, u32 smb) {
    const u32* srcb = srcbuf + ((size_t)tsrc * BB + b0) * 128;
    #pragma unroll
    for (int sec = 0; sec < 2; ++sec) {
        const u32* base = srcb + sec * 64 + r * 32;
        const u32 dst = smb + (u32)(OFF_B + (sec * 2 + r) * SZ_BSLOT) * 4;
        #pragma unroll
        for (int i = 0; i < 1; ++i) {
            const int idx = threadIdx.x + i * NTHR;   // NTHR=512 covers 512 of 1024
            const int row = idx >> 3;
            const int seg = idx & 7;
            cpa16(dst + (u32)(row * BSS + seg * 4) * 4, base + (size_t)row * 128 + seg * 4);
        }
        {   // second half of the 1024 16B segments
            const int idx = threadIdx.x + NTHR;
            const int row = idx >> 3;
            const int seg = idx & 7;
            cpa16(dst + (u32)(row * BSS + seg * 4) * 4, base + (size_t)row * 128 + seg * 4);
        }
    }
    asm volatile("cp.async.commit_group;" ::: "memory");
}

// ---------------- kernel ----------------
__global__ void __launch_bounds__(NTHR, 1) lstm_fp16(Params p) {
    extern __shared__ u32 sm[];
    float* gsm = (float*)(sm + OFF_G);
    float* bs  = (float*)(sm + OFF_BS);
    float* wxs = (float*)(sm + OFF_WX);
    float* xs  = (float*)(sm + OFF_XS);

    const int tid  = threadIdx.x;
    const int bid  = blockIdx.x;
    const int l    = bid >> 5;           // layer 0..3
    const int nb   = (bid >> 4) & 1;     // batch half
    const int jt   = bid & 15;           // hidden tile (16 units)
    const int j0   = jt * 16;
    const int b0   = nb * 128;

    const int wid  = tid >> 5;
    const int lane = tid & 31;
    const int lr   = lane >> 2;
    const int lc   = lane & 3;
    const int ks   = wid & 1;            // K-section
    const int nt   = (wid >> 1) & 3;     // n-tile (32 cols)
    const int mh   = wid >> 3;           // m-half (32 rows)

    const int lrow8 = ((lane >> 3) & 1) * 8 + (lane & 7);
    const int colq  = (lane >> 4) * 4;
    const u32 smb   = (u32)__cvta_generic_to_shared(sm);
    const u32 aAh   = smb + (u32)(OFF_AH + (mh * 32 + lrow8) * ALS + colq) * 4;
    const u32 aAl   = smb + (u32)(OFF_AL + (mh * 32 + lrow8) * ALS + colq) * 4;
    u32 bS[4];
    #pragma unroll
    for (int s = 0; s < 4; ++s)
        bS[s] = smb + (u32)(OFF_B + s * SZ_BSLOT + (nt * 32 + lrow8) * BSS + colq) * 4;

    // stage weights once (this block serves layer l forever)
    if (l > 0) stage_W(p.Wih[l], j0, 0, sm + OFF_AH, sm + OFF_AL);
    stage_W(p.Whh[l], j0, 128, sm + OFF_AH, sm + OFF_AL);
    if (tid < 64) {
        const int row = (tid >> 4) * HH + j0 + (tid & 15);
        bs[tid] = p.bih[l][row] + p.bhh[l][row];
        if (l == 0) wxs[tid] = p.Wih[0][row];   // W_ih0 is [4H,1]
    }
    __syncthreads();

    unsigned* barsIn  = (l > 0) ? (g_bar + ((l - 1) * 2 + nb) * TT) : nullptr;
    unsigned* barsOwn = g_bar + (l * 2 + nb) * TT;
    u32* outB = g_h[l];
    const u32* inB = (l > 0) ? g_h[l - 1] : nullptr;

    // elementwise ownership: batch col eb, 2 hidden-pairs starting jq2
    const int eb  = tid & 127;
    const int jq2 = (tid >> 7) * 2;      // 0,2,4,6
    float cc[4];
    #pragma unroll
    for (int i = 0; i < 4; ++i) cc[i] = 0.f;

    float* grW = gsm + ks * 8448;        // this warp's gate region (by section)

    for (int t = 0; t < TT; ++t) {
        if (l == 0 && tid < 128) xs[tid] = p.x[(size_t)(b0 + tid) * TT + t];

        // accumulators
        float cH[2][4][4], cL[2][4][4];
        {
            const float b00 = (ks == 0) ? bs[mh * 32 + lr] : 0.f;
            const float b01 = (ks == 0) ? bs[mh * 32 + 8 + lr] : 0.f;
            const float b10 = (ks == 0) ? bs[mh * 32 + 16 + lr] : 0.f;
            const float b11 = (ks == 0) ? bs[mh * 32 + 24 + lr] : 0.f;
            #pragma unroll
            for (int nj = 0; nj < 4; ++nj) {
                cH[0][nj][0] = b00; cH[0][nj][1] = b00; cH[0][nj][2] = b01; cH[0][nj][3] = b01;
                cH[1][nj][0] = b10; cH[1][nj][1] = b10; cH[1][nj][2] = b11; cH[1][nj][3] = b11;
                cL[0][nj][0] = 0.f; cL[0][nj][1] = 0.f; cL[0][nj][2] = 0.f; cL[0][nj][3] = 0.f;
                cL[1][nj][0] = 0.f; cL[1][nj][1] = 0.f; cL[1][nj][2] = 0.f; cL[1][nj][3] = 0.f;
            }
        }

        // one compute round: 4 kk starting at kkb, B from slot address bb
        auto round = [&](int kkb, u32 bb) {
            #pragma unroll
            for (int q = 0; q < 4; ++q) {
                const int kk = kkb + q;
                u32 Ah0[4], Ah1[4], Al0[4], Al1[4], H0[4], H1[4];
                ldsm4(Ah0, aAh + kk * 32);
                ldsm4(Ah1, aAh + ASTEPB + kk * 32);
                ldsm4(Al0, aAl + kk * 32);
                ldsm4(Al1, aAl + ASTEPB + kk * 32);
                ldsm4(H0, bb + q * 32);
                ldsm4(H1, bb + BGRPB + q * 32);
                mma16816(cH[0][0], Ah0, H0[0], H0[2]);
                mma16816(cH[0][1], Ah0, H0[1], H0[3]);
                mma16816(cH[0][2], Ah0, H1[0], H1[2]);
                mma16816(cH[0][3], Ah0, H1[1], H1[3]);
                mma16816(cH[1][0], Ah1, H0[0], H0[2]);
                mma16816(cH[1][1], Ah1, H0[1], H0[3]);
                mma16816(cH[1][2], Ah1, H1[0], H1[2]);
                mma16816(cH[1][3], Ah1, H1[1], H1[3]);
                mma16816(cL[0][0], Al0, H0[0], H0[2]);
                mma16816(cL[0][1], Al0, H0[1], H0[3]);
                mma16816(cL[0][2], Al0, H1[0], H1[2]);
                mma16816(cL[0][3], Al0, H1[1], H1[3]);
                mma16816(cL[1][0], Al1, H0[0], H0[2]);
                mma16816(cL[1][1], Al1, H0[1], H0[3]);
                mma16816(cL[1][2], Al1, H1[0], H1[2]);
                mma16816(cL[1][3], Al1, H1[1], H1[3]);
            }
        };

        if (l > 0) {
            if (tid == 0) poll_ge(&barsIn[t], 16);
            __syncthreads();
            issue_pair(inB, t, 0, b0, smb);
            issue_pair(inB, t, 1, b0, smb);
            // round in-0
            asm volatile("cp.async.wait_group 1;" ::: "memory");
            if (t > 0 && tid == 0) poll_ge(&barsOwn[t - 1], 16);
            __syncthreads();
            round(ks * 8 + 0, bS[ks * 2 + 0]);
            __syncthreads();
            if (t > 0) issue_pair(outB, t - 1, 0, b0, smb);
            // round in-1
            if (t > 0) { asm volatile("cp.async.wait_group 1;" ::: "memory"); }
            else       { asm volatile("cp.async.wait_group 0;" ::: "memory"); }
            __syncthreads();
            round(ks * 8 + 4, bS[ks * 2 + 1]);
            __syncthreads();
            if (t > 0) issue_pair(outB, t - 1, 1, b0, smb);
        } else {
            if (t > 0 && tid == 0) poll_ge(&barsOwn[t - 1], 16);
            __syncthreads();            // publishes xs too
            if (t > 0) {
                issue_pair(outB, t - 1, 0, b0, smb);
                issue_pair(outB, t - 1, 1, b0, smb);
            }
            // rank-1 input term (section 0 only)
            if (ks == 0) {
                #pragma unroll
                for (int mi = 0; mi < 2; ++mi) {
                    const float w0 = wxs[mh * 32 + mi * 16 + lr];
                    const float w1 = wxs[mh * 32 + mi * 16 + 8 + lr];
                    #pragma unroll
                    for (int nj = 0; nj < 4; ++nj) {
                        const int col = nt * 32 + nj * 8 + 2 * lc;
                        const float xv0 = xs[col], xv1 = xs[col + 1];
                        cH[mi][nj][0] = fmaf(w0, xv0, cH[mi][nj][0]);
                        cH[mi][nj][1] = fmaf(w0, xv1, cH[mi][nj][1]);
                        cH[mi][nj][2] = fmaf(w1, xv0, cH[mi][nj][2]);
                        cH[mi][nj][3] = fmaf(w1, xv1, cH[mi][nj][3]);
                    }
                }
            }
        }

        if (t > 0) {
            // round rec-0
            asm volatile("cp.async.wait_group 1;" ::: "memory");
            __syncthreads();
            round(16 + ks * 8 + 0, bS[ks * 2 + 0]);
            __syncthreads();
            // round rec-1
            asm volatile("cp.async.wait_group 0;" ::: "memory");
            __syncthreads();
            round(16 + ks * 8 + 4, bS[ks * 2 + 1]);
            __syncthreads();
        }

        // gate partial dump (region per section; aliases dead B slots)
        #pragma unroll
        for (int mi = 0; mi < 2; ++mi) {
            const int r0 = mh * 32 + mi * 16 + lr;
            #pragma unroll
            for (int nj = 0; nj < 4; ++nj) {
                const int col = nt * 32 + nj * 8 + 2 * lc;
                *(float2*)(grW + r0 * GS2 + col) =
                    make_float2(fmaf(cL[mi][nj][0], 0.00390625f, cH[mi][nj][0]),
                                fmaf(cL[mi][nj][1], 0.00390625f, cH[mi][nj][1]));
                *(float2*)(grW + (r0 + 8) * GS2 + col) =
                    make_float2(fmaf(cL[mi][nj][2], 0.00390625f, cH[mi][nj][2]),
                                fmaf(cL[mi][nj][3], 0.00390625f, cH[mi][nj][3]));
            }
        }
        __syncthreads();

        // elementwise: 2 hidden pairs (4 units) x 1 batch col per thread
        {
            u32 hw[2];
            #pragma unroll
            for (int pp = 0; pp < 2; ++pp) {
                const int jl0 = 2 * (jq2 + pp), jl1 = jl0 + 1;
                const float ig0 = gsm[jl0 * GS2 + eb]        + gsm[8448 + jl0 * GS2 + eb];
                const float fg0 = gsm[(16 + jl0) * GS2 + eb] + gsm[8448 + (16 + jl0) * GS2 + eb];
                const float gg0 = gsm[(32 + jl0) * GS2 + eb] + gsm[8448 + (32 + jl0) * GS2 + eb];
                const float og0 = gsm[(48 + jl0) * GS2 + eb] + gsm[8448 + (48 + jl0) * GS2 + eb];
                const float ig1 = gsm[jl1 * GS2 + eb]        + gsm[8448 + jl1 * GS2 + eb];
                const float fg1 = gsm[(16 + jl1) * GS2 + eb] + gsm[8448 + (16 + jl1) * GS2 + eb];
                const float gg1 = gsm[(32 + jl1) * GS2 + eb] + gsm[8448 + (32 + jl1) * GS2 + eb];
                const float og1 = gsm[(48 + jl1) * GS2 + eb] + gsm[8448 + (48 + jl1) * GS2 + eb];

                cc[2 * pp]     = sigf(fg0) * cc[2 * pp]     + sigf(ig0) * tanhfast(gg0);
                cc[2 * pp + 1] = sigf(fg1) * cc[2 * pp + 1] + sigf(ig1) * tanhfast(gg1);
                const float h0 = sigf(og0) * tanhfast(cc[2 * pp]);
                const float h1 = sigf(og1) * tanhfast(cc[2 * pp + 1]);
                __half2 hh = __float22half2_rn(make_float2(h0, h1));
                hw[pp] = *reinterpret_cast<u32*>(&hh);
            }
            const size_t wi = ((size_t)t * BB + b0 + eb) * 128 + jt * 8 + jq2;
            *(uint2*)(outB + wi) = make_uint2(hw[0], hw[1]);
        }
        __syncthreads();
        if (tid == 0) arrive1(&barsOwn[t]);
    }

    // completion + final FC
    __syncthreads();
    if (tid == 0) arrive1(&g_fin);

    if (bid == 0) {
        if (tid == 0) poll_ge(&g_fin, NBLK);
        __syncthreads();

        if (tid < BB) {
            const int b = tid;
            float acc = p.fcb[0];
            const u32* bh = g_h[3] + ((size_t)(TT - 1) * BB + b) * 128;
            #pragma unroll 4
            for (int k2 = 0; k2 < 128; ++k2) {
                const u32 hv = bh[k2];
                const __half2 h2 = *reinterpret_cast<const __half2*>(&hv);
                const float2 hf = __half22float2(h2);
                const float2 w = *(const float2*)(p.fcW + 2 * k2);
                acc = fmaf(w.x, hf.x, fmaf(w.y, hf.y, acc));
            }
            p.out[b] = acc;
        }

        for (int i = tid; i < LL * 2 * TT; i += NTHR) g_bar[i] = 0;
        if (tid == 0) g_fin = 0;
        __threadfence();
    }
}

extern "C" void kernel_launch(void* const* d_in, const int* in_sizes, int n_in,
                              void* d_out, int out_size) {
    (void)in_sizes; (void)n_in; (void)out_size;
    Params p;
    p.x = (const float*)d_in[0];
    for (int l = 0; l < LL; ++l) {
        p.Wih[l] = (const float*)d_in[1 + 4 * l];
        p.Whh[l] = (const float*)d_in[2 + 4 * l];
        p.bih[l] = (const float*)d_in[3 + 4 * l];
        p.bhh[l] = (const float*)d_in[4 + 4 * l];
    }
    p.fcW = (const float*)d_in[17];
    p.fcb = (const float*)d_in[18];
    p.out = (float*)d_out;

    cudaFuncSetAttribute(lstm_fp16, cudaFuncAttributeMaxDynamicSharedMemorySize, SMEM_BYTES);
    lstm_fp16<<<NBLK, NTHR, SMEM_BYTES>>>(p);
}

// round 15
// speedup vs baseline: 2.1640x; 1.1896x over previous
#include <cuda_runtime.h>
#include <cuda_fp16.h>
#include <math.h>

typedef unsigned int u32;

#define BB 256
#define TT 512
#define HH 256
#define LL 4
#define NBLK 128
#define NTHR 512

#define ALS 260            // A row stride (words): 256 k2 (concat K=512 fp16 pairs) + 4 pad
#define BSS 36             // B slot row stride (words): 32 k2 + 4 pad
#define GS2 132            // gate region row stride (n=128 + 4)

#define SZ_AH (64 * ALS)       // 16640 words per A half (hi or scaled-lo)
#define SZ_BSLOT 4608          // 128 rows * 36 words (one K=64 chunk, hi-only)
#define OFF_AH 0
#define OFF_AL SZ_AH
#define OFF_B  (2 * SZ_AH)                  // 4 chunk slots: sec0r0, sec0r1, sec1r0, sec1r1
#define OFF_G  OFF_B                        // 2 gate regions (16896 <= 18432 words) alias slots
#define OFF_BS (OFF_B + 4 * SZ_BSLOT)       // bias [64]
#define OFF_WX (OFF_BS + 64)                // layer-0 rank-1 weight [64]
#define OFF_XS (OFF_WX + 64)                // layer-0 x tile [128]
#define SMEM_WORDS (OFF_XS + 128)           // 51968 words
#define SMEM_BYTES (SMEM_WORDS * 4)         // ~208 KB

#define ASTEPB (16 * ALS * 4)   // m16 frag row step in A (bytes)
#define BGRPB  (16 * BSS * 4)   // second n16 group step in B slot (bytes)

// ---------------- device scratch ----------------
// h per layer, batch-major packed fp16 pairs: word (t, b, k2) = {h[2k2], h[2k2+1]}
__device__ __align__(128) u32 g_h[LL][(size_t)TT * BB * 128];
__device__ unsigned g_bar[LL * 2 * TT];    // [l][nb][t], target 16 arrivals
__device__ unsigned g_fin;

struct Params {
    const float* x;
    const float* Wih[LL];
    const float* Whh[LL];
    const float* bih[LL];
    const float* bhh[LL];
    const float* fcW;
    const float* fcb;
    float* out;
};

// ---------------- helpers ----------------
__device__ __forceinline__ float sigf(float v) {
    return __fdividef(1.0f, 1.0f + __expf(-v));
}
__device__ __forceinline__ float tanhfast(float v) {
    return 1.0f - __fdividef(2.0f, __expf(2.0f * v) + 1.0f);
}

__device__ __forceinline__ void mma16816(float c[4], const u32 a[4], u32 b0, u32 b1) {
    asm("mma.sync.aligned.m16n8k16.row.col.f32.f16.f16.f32 "
        "{%0,%1,%2,%3}, {%4,%5,%6,%7}, {%8,%9}, {%0,%1,%2,%3};"
        : "+f"(c[0]), "+f"(c[1]), "+f"(c[2]), "+f"(c[3])
        : "r"(a[0]), "r"(a[1]), "r"(a[2]), "r"(a[3]), "r"(b0), "r"(b1));
}

__device__ __forceinline__ void ldsm4(u32* r, u32 addr) {
    asm volatile("ldmatrix.sync.aligned.m8n8.x4.shared.b16 {%0,%1,%2,%3}, [%4];"
                 : "=r"(r[0]), "=r"(r[1]), "=r"(r[2]), "=r"(r[3]) : "r"(addr));
}

__device__ __forceinline__ void poll_ge(unsigned* p, unsigned target) {
    unsigned v;
    asm volatile("ld.acquire.gpu.global.u32 %0, [%1];" : "=r"(v) : "l"(p) : "memory");
    while (v < target) {
        __nanosleep(32);
        asm volatile("ld.acquire.gpu.global.u32 %0, [%1];" : "=r"(v) : "l"(p) : "memory");
    }
}
__device__ __forceinline__ void arrive1(unsigned* p) {
    asm volatile("red.release.gpu.global.add.u32 [%0], %1;" :: "l"(p), "r"(1u) : "memory");
}

__device__ __forceinline__ void cpa16(u32 saddr, const u32* g) {
    asm volatile("cp.async.cg.shared.global [%0], [%1], 16;" :: "r"(saddr), "l"(g) : "memory");
}

// stage one 64x256 fp32 weight slice into A smem (fp16 hi + fp16 lo*256) at k2 col offset co
__device__ __forceinline__ void stage_W(const float* __restrict__ W, int j0, int co,
                                        u32* __restrict__ sh, u32* __restrict__ sl) {
    for (int i = threadIdx.x; i < 64 * 128; i += NTHR) {
        const int m = i >> 7;
        const int k2 = i & 127;
        const int row = (m >> 4) * HH + j0 + (m & 15);
        const float2 w = *(const float2*)(W + (size_t)row * HH + 2 * k2);
        const __half hx = __float2half_rn(w.x);
        const __half hy = __float2half_rn(w.y);
        const __half lx = __float2half_rn((w.x - __half2float(hx)) * 256.0f);
        const __half ly = __float2half_rn((w.y - __half2float(hy)) * 256.0f);
        __half2 h2 = __halves2half2(hx, hy);
        __half2 l2 = __halves2half2(lx, ly);
        sh[m * ALS + co + k2] = *reinterpret_cast<u32*>(&h2);
        sl[m * ALS + co + k2] = *reinterpret_cast<u32*>(&l2);
    }
}

// issue both sections' round-r chunks from srcbuf at time tsrc (one commit group)
__device__ __forceinline__ void issue_pair(const u32* __restrict__ srcbuf, int tsrc, int r,
                                           int b0, u32 smb) {
    const u32* srcb = srcbuf + ((size_t)tsrc * BB + b0) * 128;
    #pragma unroll
    for (int sec = 0; sec < 2; ++sec) {
        const u32* base = srcb + sec * 64 + r * 32;
        const u32 dst = smb + (u32)(OFF_B + (sec * 2 + r) * SZ_BSLOT) * 4;
        {
            const int idx = threadIdx.x;
            const int row = idx >> 3;
            const int seg = idx & 7;
            cpa16(dst + (u32)(row * BSS + seg * 4) * 4, base + (size_t)row * 128 + seg * 4);
        }
        {
            const int idx = threadIdx.x + NTHR;
            const int row = idx >> 3;
            const int seg = idx & 7;
            cpa16(dst + (u32)(row * BSS + seg * 4) * 4, base + (size_t)row * 128 + seg * 4);
        }
    }
    asm volatile("cp.async.commit_group;" ::: "memory");
}

// ---------------- kernel ----------------
__global__ void __launch_bounds__(NTHR, 1) lstm_fp16b(Params p) {
    extern __shared__ u32 sm[];
    float* gsm = (float*)(sm + OFF_G);
    float* bs  = (float*)(sm + OFF_BS);
    float* wxs = (float*)(sm + OFF_WX);
    float* xs  = (float*)(sm + OFF_XS);

    const int tid  = threadIdx.x;
    const int bid  = blockIdx.x;
    const int l    = bid >> 5;           // layer 0..3
    const int nb   = (bid >> 4) & 1;     // batch half
    const int jt   = bid & 15;           // hidden tile (16 units)
    const int j0   = jt * 16;
    const int b0   = nb * 128;

    const int wid  = tid >> 5;
    const int lane = tid & 31;
    const int lr   = lane >> 2;
    const int lc   = lane & 3;
    const int ks   = wid & 1;            // K-section
    const int nt   = (wid >> 1) & 3;     // n-tile (32 cols)
    const int mh   = wid >> 3;           // m-half (32 rows)

    const int lrow8 = ((lane >> 3) & 1) * 8 + (lane & 7);
    const int colq  = (lane >> 4) * 4;
    const u32 smb   = (u32)__cvta_generic_to_shared(sm);
    const u32 aAh   = smb + (u32)(OFF_AH + (mh * 32 + lrow8) * ALS + colq) * 4;
    const u32 aAl   = smb + (u32)(OFF_AL + (mh * 32 + lrow8) * ALS + colq) * 4;
    u32 bS[4];
    #pragma unroll
    for (int s = 0; s < 4; ++s)
        bS[s] = smb + (u32)(OFF_B + s * SZ_BSLOT + (nt * 32 + lrow8) * BSS + colq) * 4;

    // stage weights once (this block serves layer l forever)
    if (l > 0) stage_W(p.Wih[l], j0, 0, sm + OFF_AH, sm + OFF_AL);
    stage_W(p.Whh[l], j0, 128, sm + OFF_AH, sm + OFF_AL);
    if (tid < 64) {
        const int row = (tid >> 4) * HH + j0 + (tid & 15);
        bs[tid] = p.bih[l][row] + p.bhh[l][row];
        if (l == 0) wxs[tid] = p.Wih[0][row];   // W_ih0 is [4H,1]
    }
    __syncthreads();

    unsigned* barsIn  = (l > 0) ? (g_bar + ((l - 1) * 2 + nb) * TT) : nullptr;
    unsigned* barsOwn = g_bar + (l * 2 + nb) * TT;
    u32* outB = g_h[l];
    const u32* inB = (l > 0) ? g_h[l - 1] : nullptr;

    // elementwise ownership: batch col eb, 2 hidden-pairs starting jq2
    const int eb  = tid & 127;
    const int jq2 = (tid >> 7) * 2;      // 0,2,4,6
    float cc[4];
    #pragma unroll
    for (int i = 0; i < 4; ++i) cc[i] = 0.f;

    float* grW = gsm + ks * 8448;        // this warp's gate region (by section)

    for (int t = 0; t < TT; ++t) {
        if (l == 0 && tid < 128) xs[tid] = p.x[(size_t)(b0 + tid) * TT + t];

        // accumulators
        float cH[2][4][4], cL[2][4][4];
        {
            const float b00 = (ks == 0) ? bs[mh * 32 + lr] : 0.f;
            const float b01 = (ks == 0) ? bs[mh * 32 + 8 + lr] : 0.f;
            const float b10 = (ks == 0) ? bs[mh * 32 + 16 + lr] : 0.f;
            const float b11 = (ks == 0) ? bs[mh * 32 + 24 + lr] : 0.f;
            #pragma unroll
            for (int nj = 0; nj < 4; ++nj) {
                cH[0][nj][0] = b00; cH[0][nj][1] = b00; cH[0][nj][2] = b01; cH[0][nj][3] = b01;
                cH[1][nj][0] = b10; cH[1][nj][1] = b10; cH[1][nj][2] = b11; cH[1][nj][3] = b11;
                cL[0][nj][0] = 0.f; cL[0][nj][1] = 0.f; cL[0][nj][2] = 0.f; cL[0][nj][3] = 0.f;
                cL[1][nj][0] = 0.f; cL[1][nj][1] = 0.f; cL[1][nj][2] = 0.f; cL[1][nj][3] = 0.f;
            }
        }

        // hi-only round (input projection half): 4 kk from kkb, B slot bb
        auto roundH = [&](int kkb, u32 bb) {
            #pragma unroll
            for (int q = 0; q < 4; ++q) {
                const int kk = kkb + q;
                u32 Ah0[4], Ah1[4], H0[4], H1[4];
                ldsm4(Ah0, aAh + kk * 32);
                ldsm4(Ah1, aAh + ASTEPB + kk * 32);
                ldsm4(H0, bb + q * 32);
                ldsm4(H1, bb + BGRPB + q * 32);
                mma16816(cH[0][0], Ah0, H0[0], H0[2]);
                mma16816(cH[0][1], Ah0, H0[1], H0[3]);
                mma16816(cH[0][2], Ah0, H1[0], H1[2]);
                mma16816(cH[0][3], Ah0, H1[1], H1[3]);
                mma16816(cH[1][0], Ah1, H0[0], H0[2]);
                mma16816(cH[1][1], Ah1, H0[1], H0[3]);
                mma16816(cH[1][2], Ah1, H1[0], H1[2]);
                mma16816(cH[1][3], Ah1, H1[1], H1[3]);
            }
        };
        // hi+lo round (recurrent half)
        auto roundHL = [&](int kkb, u32 bb) {
            #pragma unroll
            for (int q = 0; q < 4; ++q) {
                const int kk = kkb + q;
                u32 Ah0[4], Ah1[4], Al0[4], Al1[4], H0[4], H1[4];
                ldsm4(Ah0, aAh + kk * 32);
                ldsm4(Ah1, aAh + ASTEPB + kk * 32);
                ldsm4(Al0, aAl + kk * 32);
                ldsm4(Al1, aAl + ASTEPB + kk * 32);
                ldsm4(H0, bb + q * 32);
                ldsm4(H1, bb + BGRPB + q * 32);
                mma16816(cH[0][0], Ah0, H0[0], H0[2]);
                mma16816(cH[0][1], Ah0, H0[1], H0[3]);
                mma16816(cH[0][2], Ah0, H1[0], H1[2]);
                mma16816(cH[0][3], Ah0, H1[1], H1[3]);
                mma16816(cH[1][0], Ah1, H0[0], H0[2]);
                mma16816(cH[1][1], Ah1, H0[1], H0[3]);
                mma16816(cH[1][2], Ah1, H1[0], H1[2]);
                mma16816(cH[1][3], Ah1, H1[1], H1[3]);
                mma16816(cL[0][0], Al0, H0[0], H0[2]);
                mma16816(cL[0][1], Al0, H0[1], H0[3]);
                mma16816(cL[0][2], Al0, H1[0], H1[2]);
                mma16816(cL[0][3], Al0, H1[1], H1[3]);
                mma16816(cL[1][0], Al1, H0[0], H0[2]);
                mma16816(cL[1][1], Al1, H0[1], H0[3]);
                mma16816(cL[1][2], Al1, H1[0], H1[2]);
                mma16816(cL[1][3], Al1, H1[1], H1[3]);
            }
        };

        if (l > 0) {
            // parallel polls: tid0 -> producer layer, tid1 -> own recurrence
            if (tid == 0) poll_ge(&barsIn[t], 16);
            else if (tid == 1 && t > 0) poll_ge(&barsOwn[t - 1], 16);
            __syncthreads();
            issue_pair(inB, t, 0, b0, smb);
            issue_pair(inB, t, 1, b0, smb);

            asm volatile("cp.async.wait_group 1;" ::: "memory");
            __syncthreads();                         // in0 visible
            roundH(ks * 8 + 0, bS[ks * 2 + 0]);
            asm volatile("cp.async.wait_group 0;" ::: "memory");
            __syncthreads();                         // in1 visible, in0 slot free
            if (t > 0) issue_pair(outB, t - 1, 0, b0, smb);
            roundH(ks * 8 + 4, bS[ks * 2 + 1]);
            if (t > 0) {
                asm volatile("cp.async.wait_group 0;" ::: "memory");
                __syncthreads();                     // rec0 visible, in1 slot free
                issue_pair(outB, t - 1, 1, b0, smb);
                roundHL(16 + ks * 8 + 0, bS[ks * 2 + 0]);
                asm volatile("cp.async.wait_group 0;" ::: "memory");
                __syncthreads();                     // rec1 visible, rec0 slot free
                roundHL(16 + ks * 8 + 4, bS[ks * 2 + 1]);
            }
            __syncthreads();                         // all slot reads done (gates alias slots)
        } else {
            // layer 0: rank-1 input + recurrence
            if (tid == 0 && t > 0) poll_ge(&barsOwn[t - 1], 16);
            __syncthreads();                         // publishes xs; own bar acquired
            if (t > 0) {
                issue_pair(outB, t - 1, 0, b0, smb);
                issue_pair(outB, t - 1, 1, b0, smb);
            }
            if (ks == 0) {
                #pragma unroll
                for (int mi = 0; mi < 2; ++mi) {
                    const float w0 = wxs[mh * 32 + mi * 16 + lr];
                    const float w1 = wxs[mh * 32 + mi * 16 + 8 + lr];
                    #pragma unroll
                    for (int nj = 0; nj < 4; ++nj) {
                        const int col = nt * 32 + nj * 8 + 2 * lc;
                        const float xv0 = xs[col], xv1 = xs[col + 1];
                        cH[mi][nj][0] = fmaf(w0, xv0, cH[mi][nj][0]);
                        cH[mi][nj][1] = fmaf(w0, xv1, cH[mi][nj][1]);
                        cH[mi][nj][2] = fmaf(w1, xv0, cH[mi][nj][2]);
                        cH[mi][nj][3] = fmaf(w1, xv1, cH[mi][nj][3]);
                    }
                }
            }
            if (t > 0) {
                asm volatile("cp.async.wait_group 1;" ::: "memory");
                __syncthreads();                     // rec0 visible
                roundHL(16 + ks * 8 + 0, bS[ks * 2 + 0]);
                asm volatile("cp.async.wait_group 0;" ::: "memory");
                __syncthreads();                     // rec1 visible
                roundHL(16 + ks * 8 + 4, bS[ks * 2 + 1]);
            }
            __syncthreads();                         // slot reads done before gate dump
        }

        // gate partial dump (region per section; aliases dead B slots)
        #pragma unroll
        for (int mi = 0; mi < 2; ++mi) {
            const int r0 = mh * 32 + mi * 16 + lr;
            #pragma unroll
            for (int nj = 0; nj < 4; ++nj) {
                const int col = nt * 32 + nj * 8 + 2 * lc;
                *(float2*)(grW + r0 * GS2 + col) =
                    make_float2(fmaf(cL[mi][nj][0], 0.00390625f, cH[mi][nj][0]),
                                fmaf(cL[mi][nj][1], 0.00390625f, cH[mi][nj][1]));
                *(float2*)(grW + (r0 + 8) * GS2 + col) =
                    make_float2(fmaf(cL[mi][nj][2], 0.00390625f, cH[mi][nj][2]),
                                fmaf(cL[mi][nj][3], 0.00390625f, cH[mi][nj][3]));
            }
        }
        __syncthreads();

        // elementwise: 2 hidden pairs (4 units) x 1 batch col per thread
        {
            u32 hw[2];
            #pragma unroll
            for (int pp = 0; pp < 2; ++pp) {
                const int jl0 = 2 * (jq2 + pp), jl1 = jl0 + 1;
                const float ig0 = gsm[jl0 * GS2 + eb]        + gsm[8448 + jl0 * GS2 + eb];
                const float fg0 = gsm[(16 + jl0) * GS2 + eb] + gsm[8448 + (16 + jl0) * GS2 + eb];
                const float gg0 = gsm[(32 + jl0) * GS2 + eb] + gsm[8448 + (32 + jl0) * GS2 + eb];
                const float og0 = gsm[(48 + jl0) * GS2 + eb] + gsm[8448 + (48 + jl0) * GS2 + eb];
                const float ig1 = gsm[jl1 * GS2 + eb]        + gsm[8448 + jl1 * GS2 + eb];
                const float fg1 = gsm[(16 + jl1) * GS2 + eb] + gsm[8448 + (16 + jl1) * GS2 + eb];
                const float gg1 = gsm[(32 + jl1) * GS2 + eb] + gsm[8448 + (32 + jl1) * GS2 + eb];
                const float og1 = gsm[(48 + jl1) * GS2 + eb] + gsm[8448 + (48 + jl1) * GS2 + eb];

                cc[2 * pp]     = sigf(fg0) * cc[2 * pp]     + sigf(ig0) * tanhfast(gg0);
                cc[2 * pp + 1] = sigf(fg1) * cc[2 * pp + 1] + sigf(ig1) * tanhfast(gg1);
                const float h0 = sigf(og0) * tanhfast(cc[2 * pp]);
                const float h1 = sigf(og1) * tanhfast(cc[2 * pp + 1]);
                __half2 hh = __float22half2_rn(make_float2(h0, h1));
                hw[pp] = *reinterpret_cast<u32*>(&hh);
            }
            const size_t wi = ((size_t)t * BB + b0 + eb) * 128 + jt * 8 + jq2;
            *(uint2*)(outB + wi) = make_uint2(hw[0], hw[1]);
        }
        __syncthreads();
        if (tid == 0) arrive1(&barsOwn[t]);
    }

    // completion + final FC
    __syncthreads();
    if (tid == 0) arrive1(&g_fin);

    if (bid == 0) {
        if (tid == 0) poll_ge(&g_fin, NBLK);
        __syncthreads();

        if (tid < BB) {
            const int b = tid;
            float acc = p.fcb[0];
            const u32* bh = g_h[3] + ((size_t)(TT - 1) * BB + b) * 128;
            #pragma unroll 4
            for (int k2 = 0; k2 < 128; ++k2) {
                const u32 hv = bh[k2];
                const __half2 h2 = *reinterpret_cast<const __half2*>(&hv);
                const float2 hf = __half22float2(h2);
                const float2 w = *(const float2*)(p.fcW + 2 * k2);
                acc = fmaf(w.x, hf.x, fmaf(w.y, hf.y, acc));
            }
            p.out[b] = acc;
        }

        for (int i = tid; i < LL * 2 * TT; i += NTHR) g_bar[i] = 0;
        if (tid == 0) g_fin = 0;
        __threadfence();
    }
}

extern "C" void kernel_launch(void* const* d_in, const int* in_sizes, int n_in,
                              void* d_out, int out_size) {
    (void)in_sizes; (void)n_in; (void)out_size;
    Params p;
    p.x = (const float*)d_in[0];
    for (int l = 0; l < LL; ++l) {
        p.Wih[l] = (const float*)d_in[1 + 4 * l];
        p.Whh[l] = (const float*)d_in[2 + 4 * l];
        p.bih[l] = (const float*)d_in[3 + 4 * l];
        p.bhh[l] = (const float*)d_in[4 + 4 * l];
    }
    p.fcW = (const float*)d_in[17];
    p.fcb = (const float*)d_in[18];
    p.out = (float*)d_out;

    cudaFuncSetAttribute(lstm_fp16b, cudaFuncAttributeMaxDynamicSharedMemorySize, SMEM_BYTES);
    lstm_fp16b<<<NBLK, NTHR, SMEM_BYTES>>>(p);
}

// round 17
// speedup vs baseline: 2.6739x; 1.2356x over previous
#include <cuda_runtime.h>
#include <cuda_fp16.h>
#include <math.h>

typedef unsigned int u32;

#define BB 256
#define TT 512
#define HH 256
#define LL 4
#define NBLK 128
#define NTHR 512

#define ALS 260            // A row stride (words): 256 k2 (concat K=512 fp16 pairs) + 4 pad
#define BSS 36             // B slot row stride (words): 32 k2 + 4 pad
#define GS2 132            // gate region row stride (n=128 + 4)

#define SZ_AH (64 * ALS)       // 16640 words (A hi)
#define SZ_BSLOT 4608          // 128 rows * 36 words (one K=64 chunk)
#define OFF_AH 0
#define OFF_B  SZ_AH                        // 4 chunk slots: sec0r0, sec0r1, sec1r0, sec1r1
#define OFF_G  OFF_B                        // 2 gate regions (16896 <= 18432 words) alias slots
#define OFF_BS (OFF_B + 4 * SZ_BSLOT)       // bias [64]
#define OFF_WX (OFF_BS + 64)                // layer-0 rank-1 weight [64]
#define OFF_XS (OFF_WX + 64)                // layer-0 x tile [128]
#define SMEM_WORDS (OFF_XS + 128)
#define SMEM_BYTES (SMEM_WORDS * 4)         // ~142 KB

#define ASTEPB (16 * ALS * 4)   // m16 frag row step in A (bytes)
#define BGRPB  (16 * BSS * 4)   // second n16 group step in B slot (bytes)

// ---------------- device scratch ----------------
// h per layer, batch-major packed fp16 pairs: word (t, b, k2) = {h[2k2], h[2k2+1]}
__device__ __align__(128) u32 g_h[LL][(size_t)TT * BB * 128];
__device__ unsigned g_bar[LL * 2 * TT];    // [l][nb][t], target 16 arrivals
__device__ unsigned g_fin;

struct Params {
    const float* x;
    const float* Wih[LL];
    const float* Whh[LL];
    const float* bih[LL];
    const float* bhh[LL];
    const float* fcW;
    const float* fcb;
    float* out;
};

// ---------------- helpers ----------------
__device__ __forceinline__ float sigf(float v) {
    return __fdividef(1.0f, 1.0f + __expf(-v));
}
__device__ __forceinline__ float tanhfast(float v) {
    return 1.0f - __fdividef(2.0f, __expf(2.0f * v) + 1.0f);
}

__device__ __forceinline__ void mma16816(float c[4], const u32 a[4], u32 b0, u32 b1) {
    asm("mma.sync.aligned.m16n8k16.row.col.f32.f16.f16.f32 "
        "{%0,%1,%2,%3}, {%4,%5,%6,%7}, {%8,%9}, {%0,%1,%2,%3};"
        : "+f"(c[0]), "+f"(c[1]), "+f"(c[2]), "+f"(c[3])
        : "r"(a[0]), "r"(a[1]), "r"(a[2]), "r"(a[3]), "r"(b0), "r"(b1));
}

__device__ __forceinline__ void ldsm4(u32* r, u32 addr) {
    asm volatile("ldmatrix.sync.aligned.m8n8.x4.shared.b16 {%0,%1,%2,%3}, [%4];"
                 : "=r"(r[0]), "=r"(r[1]), "=r"(r[2]), "=r"(r[3]) : "r"(addr));
}

__device__ __forceinline__ void poll_ge(unsigned* p, unsigned target) {
    unsigned v;
    asm volatile("ld.acquire.gpu.global.u32 %0, [%1];" : "=r"(v) : "l"(p) : "memory");
    while (v < target) {
        __nanosleep(32);
        asm volatile("ld.acquire.gpu.global.u32 %0, [%1];" : "=r"(v) : "l"(p) : "memory");
    }
}
__device__ __forceinline__ void arrive1(unsigned* p) {
    asm volatile("red.release.gpu.global.add.u32 [%0], %1;" :: "l"(p), "r"(1u) : "memory");
}

__device__ __forceinline__ void cpa16(u32 saddr, const u32* g) {
    asm volatile("cp.async.cg.shared.global [%0], [%1], 16;" :: "r"(saddr), "l"(g) : "memory");
}

// stage one 64x256 fp32 weight slice into A smem (fp16) at k2 col offset co
__device__ __forceinline__ void stage_W(const float* __restrict__ W, int j0, int co,
                                        u32* __restrict__ sh) {
    for (int i = threadIdx.x; i < 64 * 128; i += NTHR) {
        const int m = i >> 7;
        const int k2 = i & 127;
        const int row = (m >> 4) * HH + j0 + (m & 15);
        const float2 w = *(const float2*)(W + (size_t)row * HH + 2 * k2);
        __half2 h2 = __halves2half2(__float2half_rn(w.x), __float2half_rn(w.y));
        sh[m * ALS + co + k2] = *reinterpret_cast<u32*>(&h2);
    }
}

// issue both sections' round-r chunks from srcbuf at time tsrc (one commit group)
__device__ __forceinline__ void issue_pair(const u32* __restrict__ srcbuf, int tsrc, int r,
                                           int b0, u32 smb) {
    const u32* srcb = srcbuf + ((size_t)tsrc * BB + b0) * 128;
    #pragma unroll
    for (int sec = 0; sec < 2; ++sec) {
        const u32* base = srcb + sec * 64 + r * 32;
        const u32 dst = smb + (u32)(OFF_B + (sec * 2 + r) * SZ_BSLOT) * 4;
        {
            const int idx = threadIdx.x;
            const int row = idx >> 3;
            const int seg = idx & 7;
            cpa16(dst + (u32)(row * BSS + seg * 4) * 4, base + (size_t)row * 128 + seg * 4);
        }
        {
            const int idx = threadIdx.x + NTHR;
            const int row = idx >> 3;
            const int seg = idx & 7;
            cpa16(dst + (u32)(row * BSS + seg * 4) * 4, base + (size_t)row * 128 + seg * 4);
        }
    }
    asm volatile("cp.async.commit_group;" ::: "memory");
}

// ---------------- kernel ----------------
__global__ void __launch_bounds__(NTHR, 1) lstm_fp16c(Params p) {
    extern __shared__ u32 sm[];
    float* gsm = (float*)(sm + OFF_G);
    float* bs  = (float*)(sm + OFF_BS);
    float* wxs = (float*)(sm + OFF_WX);
    float* xs  = (float*)(sm + OFF_XS);

    const int tid  = threadIdx.x;
    const int bid  = blockIdx.x;
    const int l    = bid >> 5;           // layer 0..3
    const int nb   = (bid >> 4) & 1;     // batch half
    const int jt   = bid & 15;           // hidden tile (16 units)
    const int j0   = jt * 16;
    const int b0   = nb * 128;

    const int wid  = tid >> 5;
    const int lane = tid & 31;
    const int lr   = lane >> 2;
    const int lc   = lane & 3;
    const int ks   = wid & 1;            // K-section
    const int nt   = (wid >> 1) & 3;     // n-tile (32 cols)
    const int mh   = wid >> 3;           // m-half (32 rows)

    const int lrow8 = ((lane >> 3) & 1) * 8 + (lane & 7);
    const int colq  = (lane >> 4) * 4;
    const u32 smb   = (u32)__cvta_generic_to_shared(sm);
    const u32 aAh   = smb + (u32)(OFF_AH + (mh * 32 + lrow8) * ALS + colq) * 4;
    u32 bS[4];
    #pragma unroll
    for (int s = 0; s < 4; ++s)
        bS[s] = smb + (u32)(OFF_B + s * SZ_BSLOT + (nt * 32 + lrow8) * BSS + colq) * 4;

    // stage weights once (this block serves layer l forever)
    if (l > 0) stage_W(p.Wih[l], j0, 0, sm + OFF_AH);
    stage_W(p.Whh[l], j0, 128, sm + OFF_AH);
    if (tid < 64) {
        const int row = (tid >> 4) * HH + j0 + (tid & 15);
        bs[tid] = p.bih[l][row] + p.bhh[l][row];
        if (l == 0) wxs[tid] = p.Wih[0][row];   // W_ih0 is [4H,1]
    }
    __syncthreads();

    unsigned* barsIn  = (l > 0) ? (g_bar + ((l - 1) * 2 + nb) * TT) : nullptr;
    unsigned* barsOwn = g_bar + (l * 2 + nb) * TT;
    u32* outB = g_h[l];
    const u32* inB = (l > 0) ? g_h[l - 1] : nullptr;

    // elementwise ownership: batch col eb, 2 hidden-pairs starting jq2
    const int eb  = tid & 127;
    const int jq2 = (tid >> 7) * 2;      // 0,2,4,6
    float cc[4];
    #pragma unroll
    for (int i = 0; i < 4; ++i) cc[i] = 0.f;

    float* grW = gsm + ks * 8448;        // this warp's gate region (by section)

    for (int t = 0; t < TT; ++t) {
        if (l == 0 && tid < 128) xs[tid] = p.x[(size_t)(b0 + tid) * TT + t];

        // accumulators
        float cH[2][4][4];
        {
            const float b00 = (ks == 0) ? bs[mh * 32 + lr] : 0.f;
            const float b01 = (ks == 0) ? bs[mh * 32 + 8 + lr] : 0.f;
            const float b10 = (ks == 0) ? bs[mh * 32 + 16 + lr] : 0.f;
            const float b11 = (ks == 0) ? bs[mh * 32 + 24 + lr] : 0.f;
            #pragma unroll
            for (int nj = 0; nj < 4; ++nj) {
                cH[0][nj][0] = b00; cH[0][nj][1] = b00; cH[0][nj][2] = b01; cH[0][nj][3] = b01;
                cH[1][nj][0] = b10; cH[1][nj][1] = b10; cH[1][nj][2] = b11; cH[1][nj][3] = b11;
            }
        }

        // single-pass round: 4 kk from kkb, B slot bb
        auto roundH = [&](int kkb, u32 bb) {
            #pragma unroll
            for (int q = 0; q < 4; ++q) {
                const int kk = kkb + q;
                u32 Ah0[4], Ah1[4], H0[4], H1[4];
                ldsm4(Ah0, aAh + kk * 32);
                ldsm4(Ah1, aAh + ASTEPB + kk * 32);
                ldsm4(H0, bb + q * 32);
                ldsm4(H1, bb + BGRPB + q * 32);
                mma16816(cH[0][0], Ah0, H0[0], H0[2]);
                mma16816(cH[0][1], Ah0, H0[1], H0[3]);
                mma16816(cH[0][2], Ah0, H1[0], H1[2]);
                mma16816(cH[0][3], Ah0, H1[1], H1[3]);
                mma16816(cH[1][0], Ah1, H0[0], H0[2]);
                mma16816(cH[1][1], Ah1, H0[1], H0[3]);
                mma16816(cH[1][2], Ah1, H1[0], H1[2]);
                mma16816(cH[1][3], Ah1, H1[1], H1[3]);
            }
        };

        if (l > 0) {
            // parallel polls: tid0 -> producer layer, tid1 -> own recurrence
            if (tid == 0) poll_ge(&barsIn[t], 16);
            else if (tid == 1 && t > 0) poll_ge(&barsOwn[t - 1], 16);
            __syncthreads();
            issue_pair(inB, t, 0, b0, smb);
            issue_pair(inB, t, 1, b0, smb);

            asm volatile("cp.async.wait_group 1;" ::: "memory");
            __syncthreads();                         // in0 visible
            roundH(ks * 8 + 0, bS[ks * 2 + 0]);
            asm volatile("cp.async.wait_group 0;" ::: "memory");
            __syncthreads();                         // in1 visible, in0 slot free
            if (t > 0) issue_pair(outB, t - 1, 0, b0, smb);
            roundH(ks * 8 + 4, bS[ks * 2 + 1]);
            if (t > 0) {
                asm volatile("cp.async.wait_group 0;" ::: "memory");
                __syncthreads();                     // rec0 visible, in1 slot free
                issue_pair(outB, t - 1, 1, b0, smb);
                roundH(16 + ks * 8 + 0, bS[ks * 2 + 0]);
                asm volatile("cp.async.wait_group 0;" ::: "memory");
                __syncthreads();                     // rec1 visible, rec0 slot free
                roundH(16 + ks * 8 + 4, bS[ks * 2 + 1]);
            }
            __syncthreads();                         // all slot reads done (gates alias slots)
        } else {
            // layer 0: rank-1 input + recurrence
            if (tid == 0 && t > 0) poll_ge(&barsOwn[t - 1], 16);
            __syncthreads();                         // publishes xs; own bar acquired
            if (t > 0) {
                issue_pair(outB, t - 1, 0, b0, smb);
                issue_pair(outB, t - 1, 1, b0, smb);
            }
            if (ks == 0) {
                #pragma unroll
                for (int mi = 0; mi < 2; ++mi) {
                    const float w0 = wxs[mh * 32 + mi * 16 + lr];
                    const float w1 = wxs[mh * 32 + mi * 16 + 8 + lr];
                    #pragma unroll
                    for (int nj = 0; nj < 4; ++nj) {
                        const int col = nt * 32 + nj * 8 + 2 * lc;
                        const float xv0 = xs[col], xv1 = xs[col + 1];
                        cH[mi][nj][0] = fmaf(w0, xv0, cH[mi][nj][0]);
                        cH[mi][nj][1] = fmaf(w0, xv1, cH[mi][nj][1]);
                        cH[mi][nj][2] = fmaf(w1, xv0, cH[mi][nj][2]);
                        cH[mi][nj][3] = fmaf(w1, xv1, cH[mi][nj][3]);
                    }
                }
            }
            if (t > 0) {
                asm volatile("cp.async.wait_group 1;" ::: "memory");
                __syncthreads();                     // rec0 visible
                roundH(16 + ks * 8 + 0, bS[ks * 2 + 0]);
                asm volatile("cp.async.wait_group 0;" ::: "memory");
                __syncthreads();                     // rec1 visible
                roundH(16 + ks * 8 + 4, bS[ks * 2 + 1]);
            }
            __syncthreads();                         // slot reads done before gate dump
        }

        // gate partial dump (region per section; aliases dead B slots)
        #pragma unroll
        for (int mi = 0; mi < 2; ++mi) {
            const int r0 = mh * 32 + mi * 16 + lr;
            #pragma unroll
            for (int nj = 0; nj < 4; ++nj) {
                const int col = nt * 32 + nj * 8 + 2 * lc;
                *(float2*)(grW + r0 * GS2 + col) =
                    make_float2(cH[mi][nj][0], cH[mi][nj][1]);
                *(float2*)(grW + (r0 + 8) * GS2 + col) =
                    make_float2(cH[mi][nj][2], cH[mi][nj][3]);
            }
        }
        __syncthreads();

        // elementwise: 2 hidden pairs (4 units) x 1 batch col per thread
        {
            u32 hw[2];
            #pragma unroll
            for (int pp = 0; pp < 2; ++pp) {
                const int jl0 = 2 * (jq2 + pp), jl1 = jl0 + 1;
                const float ig0 = gsm[jl0 * GS2 + eb]        + gsm[8448 + jl0 * GS2 + eb];
                const float fg0 = gsm[(16 + jl0) * GS2 + eb] + gsm[8448 + (16 + jl0) * GS2 + eb];
                const float gg0 = gsm[(32 + jl0) * GS2 + eb] + gsm[8448 + (32 + jl0) * GS2 + eb];
                const float og0 = gsm[(48 + jl0) * GS2 + eb] + gsm[8448 + (48 + jl0) * GS2 + eb];
                const float ig1 = gsm[jl1 * GS2 + eb]        + gsm[8448 + jl1 * GS2 + eb];
                const float fg1 = gsm[(16 + jl1) * GS2 + eb] + gsm[8448 + (16 + jl1) * GS2 + eb];
                const float gg1 = gsm[(32 + jl1) * GS2 + eb] + gsm[8448 + (32 + jl1) * GS2 + eb];
                const float og1 = gsm[(48 + jl1) * GS2 + eb] + gsm[8448 + (48 + jl1) * GS2 + eb];

                cc[2 * pp]     = sigf(fg0) * cc[2 * pp]     + sigf(ig0) * tanhfast(gg0);
                cc[2 * pp + 1] = sigf(fg1) * cc[2 * pp + 1] + sigf(ig1) * tanhfast(gg1);
                const float h0 = sigf(og0) * tanhfast(cc[2 * pp]);
                const float h1 = sigf(og1) * tanhfast(cc[2 * pp + 1]);
                __half2 hh = __float22half2_rn(make_float2(h0, h1));
                hw[pp] = *reinterpret_cast<u32*>(&hh);
            }
            const size_t wi = ((size_t)t * BB + b0 + eb) * 128 + jt * 8 + jq2;
            *(uint2*)(outB + wi) = make_uint2(hw[0], hw[1]);
        }
        __syncthreads();
        if (tid == 0) arrive1(&barsOwn[t]);
    }

    // completion + final FC
    __syncthreads();
    if (tid == 0) arrive1(&g_fin);

    if (bid == 0) {
        if (tid == 0) poll_ge(&g_fin, NBLK);
        __syncthreads();

        if (tid < BB) {
            const int b = tid;
            float acc = p.fcb[0];
            const u32* bh = g_h[3] + ((size_t)(TT - 1) * BB + b) * 128;
            #pragma unroll 4
            for (int k2 = 0; k2 < 128; ++k2) {
                const u32 hv = bh[k2];
                const __half2 h2 = *reinterpret_cast<const __half2*>(&hv);
                const float2 hf = __half22float2(h2);
                const float2 w = *(const float2*)(p.fcW + 2 * k2);
                acc = fmaf(w.x, hf.x, fmaf(w.y, hf.y, acc));
            }
            p.out[b] = acc;
        }

        for (int i = tid; i < LL * 2 * TT; i += NTHR) g_bar[i] = 0;
        if (tid == 0) g_fin = 0;
        __threadfence();
    }
}

extern "C" void kernel_launch(void* const* d_in, const int* in_sizes, int n_in,
                              void* d_out, int out_size) {
    (void)in_sizes; (void)n_in; (void)out_size;
    Params p;
    p.x = (const float*)d_in[0];
    for (int l = 0; l < LL; ++l) {
        p.Wih[l] = (const float*)d_in[1 + 4 * l];
        p.Whh[l] = (const float*)d_in[2 + 4 * l];
        p.bih[l] = (const float*)d_in[3 + 4 * l];
        p.bhh[l] = (const float*)d_in[4 + 4 * l];
    }
    p.fcW = (const float*)d_in[17];
    p.fcb = (const float*)d_in[18];
    p.out = (float*)d_out;

    cudaFuncSetAttribute(lstm_fp16c, cudaFuncAttributeMaxDynamicSharedMemorySize, SMEM_BYTES);
    lstm_fp16c<<<NBLK, NTHR, SMEM_BYTES>>>(p);
}